// round 9
// baseline (speedup 1.0000x reference)
#include <cuda_runtime.h>
#include <cuda_bf16.h>
#include <cstdint>

#define NN 110
#define CC 4096
#define NPAD 128

#define BM 128
#define BKC 64          // k per chunk
#define PITCHA 72       // bf16 elems per A smem row
#define NTH 256

#define PS (NPAD * CC)  // partial buffer stride

// -------------------- scratch (zero-initialized device globals) ------------
__device__ float g_h   [NPAD * CC];
__device__ float g_out1[NPAD * CC];
__device__ float g_Mn  [NPAD * NPAD];
__device__ float g_Wlp [NPAD * NPAD];
__device__ float g_P   [4 * PS];
// pre-split bf16 hi/lo (rows >= 110 never written -> zero)
__device__ __nv_bfloat16 g_xh[NPAD * CC], g_xl[NPAD * CC];
__device__ __nv_bfloat16 g_hh[NPAD * CC], g_hl[NPAD * CC];
__device__ __nv_bfloat16 g_ah[NPAD * CC], g_al[NPAD * CC];

// -------------------- helpers ----------------------------------------------
__device__ __forceinline__ uint32_t smem_u32(const void* p) {
    uint32_t a;
    asm("{ .reg .u64 t; cvta.to.shared.u64 t, %1; cvt.u32.u64 %0, t; }"
        : "=r"(a) : "l"(p));
    return a;
}

__device__ __forceinline__ void split2(float x0, float x1, uint32_t& hi, uint32_t& lo) {
    uint32_t h;
    asm("cvt.rn.bf16x2.f32 %0, %1, %2;" : "=r"(h) : "f"(x1), "f"(x0));
    float h0 = __uint_as_float(h << 16);
    float h1 = __uint_as_float(h & 0xFFFF0000u);
    float r0 = x0 - h0;
    float r1 = x1 - h1;
    asm("cvt.rn.bf16x2.f32 %0, %1, %2;" : "=r"(lo) : "f"(r1), "f"(r0));
    hi = h;
}

#define LDMX4(r, addr)                                                        \
    asm volatile("ldmatrix.sync.aligned.m8n8.x4.shared.b16 {%0,%1,%2,%3}, [%4];" \
        : "=r"((r)[0]), "=r"((r)[1]), "=r"((r)[2]), "=r"((r)[3]) : "r"(addr))

#define LDMX4T(r, addr)                                                       \
    asm volatile("ldmatrix.sync.aligned.m8n8.x4.trans.shared.b16 {%0,%1,%2,%3}, [%4];" \
        : "=r"((r)[0]), "=r"((r)[1]), "=r"((r)[2]), "=r"((r)[3]) : "r"(addr))

#define MMA_BF16(acc, a, b0, b1)                                              \
    asm volatile("mma.sync.aligned.m16n8k16.row.col.f32.bf16.bf16.f32 "       \
        "{%0,%1,%2,%3}, {%4,%5,%6,%7}, {%8,%9}, {%0,%1,%2,%3};"               \
        : "+f"((acc)[0]), "+f"((acc)[1]), "+f"((acc)[2]), "+f"((acc)[3])      \
        : "r"((a)[0]), "r"((a)[1]), "r"((a)[2]), "r"((a)[3]), "r"(b0), "r"(b1))

#define CP16(dst, src)                                                        \
    asm volatile("cp.async.cg.shared.global [%0], [%1], 16;" :: "r"(dst), "l"(src))
#define CP_COMMIT() asm volatile("cp.async.commit_group;" ::: "memory")
#define CP_WAIT(n)  asm volatile("cp.async.wait_group %0;" :: "n"(n) : "memory")

// ---------------------------------------------------------------------------
// Prep: Mn, Wlp (fp32)
// ---------------------------------------------------------------------------
__global__ void prep_kernel(const int* __restrict__ adj, const float* __restrict__ Wl) {
    const int j = blockIdx.x;
    const int i = threadIdx.x;
    __shared__ int sdeg[NPAD];
    int a = (i < NN && j < NN) ? (adj[i * NN + j] != 0) : 0;
    sdeg[i] = a;
    __syncthreads();
#pragma unroll
    for (int s = 64; s > 0; s >>= 1) {
        if (i < s) sdeg[i] += sdeg[i + s];
        __syncthreads();
    }
    const int deg = sdeg[0];
    const float inv = (j < NN) ? 1.0f / (float)(deg > 1 ? deg : 1) : 0.0f;
    g_Mn [j * NPAD + i] = a ? inv : 0.0f;
    g_Wlp[j * NPAD + i] = (i < NN && j < NN) ? Wl[j * NN + i] : 0.0f;
}

// ---------------------------------------------------------------------------
// Prep: split x into hi/lo bf16
// ---------------------------------------------------------------------------
__global__ void split_x_kernel(const float* __restrict__ src) {
    int e = (blockIdx.x * blockDim.x + threadIdx.x) * 8;
    if (e >= NN * CC) return;
    float4 a = *(const float4*)(src + e);
    float4 b = *(const float4*)(src + e + 4);
    uint4 hv, lv;
    split2(a.x, a.y, hv.x, lv.x);
    split2(a.z, a.w, hv.y, lv.y);
    split2(b.x, b.y, hv.z, lv.z);
    split2(b.z, b.w, hv.w, lv.w);
    *(uint4*)&g_xh[e] = hv;
    *(uint4*)&g_xl[e] = lv;
}

// ---------------------------------------------------------------------------
// Combine: s = sum P_s + bias; optional relu; fp32 out + optional bf16 pairs
// ---------------------------------------------------------------------------
__global__ void combine_kernel(const float* __restrict__ P,
                               const float* __restrict__ bias, int do_relu,
                               float* __restrict__ out,
                               __nv_bfloat16* __restrict__ outH,
                               __nv_bfloat16* __restrict__ outL) {
    int e = (blockIdx.x * blockDim.x + threadIdx.x) * 4;
    if (e >= NN * CC) return;
    float4 p0 = *(const float4*)(P + e);
    float4 p1 = *(const float4*)(P + PS + e);
    float4 p2 = *(const float4*)(P + 2 * PS + e);
    float4 p3 = *(const float4*)(P + 3 * PS + e);
    float4 bv = *(const float4*)(bias + (e & (CC - 1)));
    float4 v;
    v.x = (p0.x + p1.x) + (p2.x + p3.x) + bv.x;
    v.y = (p0.y + p1.y) + (p2.y + p3.y) + bv.y;
    v.z = (p0.z + p1.z) + (p2.z + p3.z) + bv.z;
    v.w = (p0.w + p1.w) + (p2.w + p3.w) + bv.w;
    if (do_relu) {
        v.x = fmaxf(v.x, 0.f); v.y = fmaxf(v.y, 0.f);
        v.z = fmaxf(v.z, 0.f); v.w = fmaxf(v.w, 0.f);
    }
    if (out) *(float4*)(out + e) = v;
    if (outH) {
        uint2 hv, lv;
        split2(v.x, v.y, hv.x, lv.x);
        split2(v.z, v.w, hv.y, lv.y);
        *(uint2*)(outH + e) = hv;
        *(uint2*)(outL + e) = lv;
    }
}

// ===========================================================================
// tgemmA: CTA tile 128x128, 8 warps (4m x 2n), warp tile 32x64.
// A pre-split bf16 hi/lo fetched via cp.async into a 3-stage ring.
// B fp32 converted in-kernel, 2-stage reg-staged (R8 path verbatim).
// Always writes fp32 partials to C + slice*PS. One __syncthreads per chunk.
// ===========================================================================
#define BNT 128
#define PITCHB (BNT + 8)
#define ASTG ((uint32_t)BM * PITCHA * 2u)              // 18432 per array
#define ASTAGE (2u * ASTG)                             // AH+AL = 36864
#define ABASE 0u
#define BBYTES ((uint32_t)BKC * PITCHB * 2u)           // 17408
#define BSTAGE (2u * BBYTES)                           // BH+BL = 34816
#define BBASE (3u * ASTAGE)                            // 110592
#define DSA (BBASE + 2u * BSTAGE)                      // 180224

__global__ __launch_bounds__(NTH, 1)
void tgemmA(const __nv_bfloat16* __restrict__ Ah1, const __nv_bfloat16* __restrict__ Al1,
            int lda1, int ka1,
            const float* __restrict__ B1, int ldb1,
            const __nv_bfloat16* __restrict__ Ah2, const __nv_bfloat16* __restrict__ Al2,
            int lda2, int ka2,
            const float* __restrict__ B2, int ldb2,
            int SPLITS,
            float* __restrict__ C, int ldc, int Mreal)
{
    extern __shared__ __align__(16) char dsm[];
    const uint32_t sb = smem_u32(dsm);

    const int tid = threadIdx.x;
    const int wid = tid >> 5;
    const int lid = tid & 31;
    const int ms = wid & 3;
    const int ns = wid >> 2;
    const int n0 = blockIdx.x * BNT;
    const int slice = blockIdx.y;

    const int pair = slice / SPLITS;
    const int q    = slice % SPLITS;
    const __nv_bfloat16* Ah = pair ? Ah2 : Ah1;
    const __nv_bfloat16* Al = pair ? Al2 : Al1;
    const float* B = pair ? B2 : B1;
    const int lda = pair ? lda2 : lda1;
    const int ldb = pair ? ldb2 : ldb1;
    const int kaeff = (pair ? ka2 : ka1) / SPLITS;
    const int kbase = q * kaeff;
    const int T = kaeff / BKC;

    // cp.async A mapping: row = tid>>1, half = (tid&1)*32 elems, 4x16B per array
    const int car = tid >> 1;
    const int cah = (tid & 1) * 32;
    // B loader: 64 k x 128 n fp32; thread -> (k row, 32 n)
    const int bkq = tid >> 2;
    const int bnq = (tid & 3) * 32;

    float acc[2][8][4];
#pragma unroll
    for (int a = 0; a < 2; ++a)
#pragma unroll
        for (int b = 0; b < 8; ++b)
#pragma unroll
            for (int c = 0; c < 4; ++c) acc[a][b][c] = 0.0f;

    // fragment lane offsets (validated layouts)
    const uint32_t aoff = (((uint32_t)(ms * 32 + (lid & 15)) * PITCHA) +
                           ((lid >> 4) & 1) * 8u) * 2u;                 // within A array
    const uint32_t boff = (((uint32_t)(lid & 15) * PITCHB) +
                           (uint32_t)(ns * 64 + (lid >> 4) * 8)) * 2u;  // within B array

    float4 fbr[8];

#define CPA(T_)                                                                \
    do {                                                                       \
        uint32_t ab_ = sb + ABASE + (uint32_t)((T_) % 3) * ASTAGE;             \
        int k0_ = kbase + (T_) * BKC;                                          \
        size_t go_ = (size_t)car * lda + k0_ + cah;                            \
        uint32_t so_ = ((uint32_t)car * PITCHA + (uint32_t)cah) * 2u;          \
        _Pragma("unroll")                                                      \
        for (int j = 0; j < 4; ++j) {                                          \
            CP16(ab_ + so_ + j * 16u,        Ah + go_ + j * 8);                \
            CP16(ab_ + ASTG + so_ + j * 16u, Al + go_ + j * 8);                \
        }                                                                      \
    } while (0)

#define LDGB(T_)                                                               \
    do {                                                                       \
        int k0_ = kbase + (T_) * BKC;                                          \
        const float* p_ = B + (size_t)(k0_ + bkq) * ldb + n0 + bnq;            \
        _Pragma("unroll")                                                      \
        for (int j = 0; j < 8; ++j)                                            \
            fbr[j] = *(const float4*)(p_ + j * 4);                             \
    } while (0)

#define STSB(T_)                                                               \
    do {                                                                       \
        uint32_t bb_ = sb + BBASE + (uint32_t)((T_) & 1) * BSTAGE;             \
        uint32_t o_ = ((uint32_t)bkq * PITCHB + (uint32_t)bnq) * 2u;           \
        _Pragma("unroll")                                                      \
        for (int j = 0; j < 8; j += 2) {                                       \
            uint4 hv, lv;                                                      \
            split2(fbr[j].x,     fbr[j].y,     hv.x, lv.x);                    \
            split2(fbr[j].z,     fbr[j].w,     hv.y, lv.y);                    \
            split2(fbr[j + 1].x, fbr[j + 1].y, hv.z, lv.z);                    \
            split2(fbr[j + 1].z, fbr[j + 1].w, hv.w, lv.w);                    \
            *(uint4*)(size_t)(bb_ + o_ + j * 8u) = hv;  /* placeholder */      \
        }                                                                      \
    } while (0)

#undef STSB
    // (generic-pointer smem stores via dsm char*; recompute char* base)
#define STSB(T_)                                                               \
    do {                                                                       \
        char* bb_ = dsm + BBASE + (size_t)((T_) & 1) * BSTAGE;                 \
        uint32_t o_ = ((uint32_t)bkq * PITCHB + (uint32_t)bnq) * 2u;           \
        _Pragma("unroll")                                                      \
        for (int j = 0; j < 8; j += 2) {                                       \
            uint4 hv, lv;                                                      \
            split2(fbr[j].x,     fbr[j].y,     hv.x, lv.x);                    \
            split2(fbr[j].z,     fbr[j].w,     hv.y, lv.y);                    \
            split2(fbr[j + 1].x, fbr[j + 1].y, hv.z, lv.z);                    \
            split2(fbr[j + 1].z, fbr[j + 1].w, hv.w, lv.w);                    \
            *(uint4*)(bb_ + o_ + j * 8u)          = hv;                        \
            *(uint4*)(bb_ + BBYTES + o_ + j * 8u) = lv;                        \
        }                                                                      \
    } while (0)

    // ---- prologue: A chunks 0,1 in flight; B chunk 0 staged, 1 in regs ----
    CPA(0); CP_COMMIT();
    CPA(1); CP_COMMIT();
    LDGB(0);
    STSB(0);
    LDGB(1);
    CP_WAIT(1);            // chunk 0 A landed
    __syncthreads();

    for (int t = 0; t < T; ++t) {
        const uint32_t abase = sb + ABASE + (uint32_t)(t % 3) * ASTAGE;
        const uint32_t bbase = sb + BBASE + (uint32_t)(t & 1) * BSTAGE;

        // ---- MMA: 4 k-steps of 16 ----
#pragma unroll
        for (int ks = 0; ks < 4; ++ks) {
            const uint32_t kA = (uint32_t)ks * 32u;
            const uint32_t kB = (uint32_t)ks * 16u * PITCHB * 2u;
            uint32_t ah[2][4], al[2][4], bh[4][4], bl[4][4];
            LDMX4(ah[0], abase + aoff + kA);
            LDMX4(ah[1], abase + aoff + 16u * PITCHA * 2u + kA);
            LDMX4(al[0], abase + ASTG + aoff + kA);
            LDMX4(al[1], abase + ASTG + aoff + 16u * PITCHA * 2u + kA);
#pragma unroll
            for (int gp = 0; gp < 4; ++gp) {
                LDMX4T(bh[gp], bbase + boff + gp * 32u + kB);
                LDMX4T(bl[gp], bbase + BBYTES + boff + gp * 32u + kB);
            }
#pragma unroll
            for (int mt = 0; mt < 2; ++mt)
#pragma unroll
                for (int nt = 0; nt < 8; ++nt) {
                    const int gp = nt >> 1, ix = (nt & 1) * 2;
                    MMA_BF16(acc[mt][nt], ah[mt], bh[gp][ix], bh[gp][ix + 1]);
                    MMA_BF16(acc[mt][nt], ah[mt], bl[gp][ix], bl[gp][ix + 1]);
                    MMA_BF16(acc[mt][nt], al[mt], bh[gp][ix], bh[gp][ix + 1]);
                }
        }

        // ---- rotate: stage B(t+1), prefetch B(t+2), cp.async A(t+2) ----
        if (t + 1 < T) STSB(t + 1);
        if (t + 2 < T) {
            LDGB(t + 2);
            CPA(t + 2); CP_COMMIT();
            CP_WAIT(1);      // A(t+1) landed
        } else {
            CP_WAIT(0);
        }
        __syncthreads();
    }
#undef CPA
#undef LDGB
#undef STSB

    // ---- epilogue: fp32 partials ----
    const int g  = lid >> 2;
    const int tq = lid & 3;
    float* Pout = C + (size_t)slice * PS;
#pragma unroll
    for (int mt = 0; mt < 2; ++mt) {
#pragma unroll
        for (int nt = 0; nt < 8; ++nt) {
            int col = n0 + ns * 64 + nt * 8 + tq * 2;
#pragma unroll
            for (int half = 0; half < 2; ++half) {
                int m = ms * 32 + mt * 16 + g + half * 8;
                if (m >= Mreal) continue;
                *(float2*)&Pout[(size_t)m * ldc + col] =
                    make_float2(acc[mt][nt][half * 2 + 0], acc[mt][nt][half * 2 + 1]);
            }
        }
    }
}

// ===========================================================================
// tgemm64: R8-proven fp32-A kernel, CTA tile 128x64. OSPL: write bf16 pairs.
// ===========================================================================
#define PITCHB64 72
#define AH64 0u
#define AL64 18432u
#define BH64 36864u
#define BB64 ((uint32_t)BKC * PITCHB64 * 2u)   // 9216
#define BL64 (BH64 + BB64)
#define ST64 (BH64 + 2u * BB64)                // 55296
#define DS64 (2u * ST64)

template<int OSPL>
__global__ __launch_bounds__(NTH, 1)
void tgemm64(const float* __restrict__ A1, int lda1, int ka1,
             const float* __restrict__ B1, int ldb1,
             const float* __restrict__ bias, int bias_mode, int do_relu,
             float* __restrict__ C,
             __nv_bfloat16* __restrict__ Ch, __nv_bfloat16* __restrict__ Cl,
             int ldc, int Mreal)
{
    extern __shared__ __align__(16) char dsm[];
    const uint32_t sb = smem_u32(dsm);

    const int tid = threadIdx.x;
    const int wid = tid >> 5;
    const int lid = tid & 31;
    const int ms = wid & 3;
    const int ns = wid >> 2;
    const int n0 = blockIdx.x * 64;

    const int T = ka1 / BKC;

    const int alrow = tid >> 4;
    const int alc   = (tid & 15) * 4;
    const int bkq = tid >> 2;
    const int bnq = (tid & 3) * 16;

    float acc[2][4][4];
#pragma unroll
    for (int a = 0; a < 2; ++a)
#pragma unroll
        for (int b = 0; b < 4; ++b)
#pragma unroll
            for (int c = 0; c < 4; ++c) acc[a][b][c] = 0.0f;

    const uint32_t aoffH = AH64 +
        (((uint32_t)(ms * 32 + (lid & 15)) * PITCHA) + ((lid >> 4) & 1) * 8u) * 2u;
    const uint32_t boff = BH64 +
        (((uint32_t)(lid & 15) * PITCHB64) + (uint32_t)(ns * 32 + (lid >> 4) * 8)) * 2u;

    float4 fa[8];
    float4 fbr[4];
    const float4 f4z = make_float4(0.f, 0.f, 0.f, 0.f);

#define LOADG(T_)                                                              \
    do {                                                                       \
        int k0_ = (T_) * BKC;                                                  \
        _Pragma("unroll")                                                      \
        for (int p = 0; p < 8; ++p) {                                          \
            int m = p * 16 + alrow;                                            \
            fa[p] = (m < Mreal) ? *(const float4*)(A1 + (size_t)m * lda1 + k0_ + alc) : f4z; \
        }                                                                      \
        const float* p_ = B1 + (size_t)(k0_ + bkq) * ldb1 + n0 + bnq;          \
        _Pragma("unroll")                                                      \
        for (int j = 0; j < 4; ++j)                                            \
            fbr[j] = *(const float4*)(p_ + j * 4);                             \
    } while (0)

#define STORE_STAGE(bufsel)                                                    \
    do {                                                                       \
        char* st = dsm + (bufsel) * ST64;                                      \
        _Pragma("unroll")                                                      \
        for (int p = 0; p < 8; ++p) {                                          \
            int row = p * 16 + alrow;                                          \
            uint32_t h0, l0, h1, l1;                                           \
            split2(fa[p].x, fa[p].y, h0, l0);                                  \
            split2(fa[p].z, fa[p].w, h1, l1);                                  \
            uint32_t off = ((uint32_t)row * PITCHA + (uint32_t)alc) * 2u;      \
            *(uint2*)(st + AH64 + off) = make_uint2(h0, h1);                   \
            *(uint2*)(st + AL64 + off) = make_uint2(l0, l1);                   \
        }                                                                      \
        {                                                                      \
            uint32_t o_ = ((uint32_t)bkq * PITCHB64 + (uint32_t)bnq) * 2u;     \
            _Pragma("unroll")                                                  \
            for (int j = 0; j < 4; j += 2) {                                   \
                uint4 hv, lv;                                                  \
                split2(fbr[j].x,     fbr[j].y,     hv.x, lv.x);                \
                split2(fbr[j].z,     fbr[j].w,     hv.y, lv.y);                \
                split2(fbr[j + 1].x, fbr[j + 1].y, hv.z, lv.z);                \
                split2(fbr[j + 1].z, fbr[j + 1].w, hv.w, lv.w);                \
                *(uint4*)(st + BH64 + o_ + j * 8u) = hv;                       \
                *(uint4*)(st + BL64 + o_ + j * 8u) = lv;                       \
            }                                                                  \
        }                                                                      \
    } while (0)

    LOADG(0);
    STORE_STAGE(0);
    if (T > 1) LOADG(1);
    __syncthreads();

    for (int t = 0; t < T; ++t) {
        const uint32_t base = sb + (uint32_t)(t & 1) * ST64;
#pragma unroll
        for (int ks = 0; ks < 4; ++ks) {
            const uint32_t kA = (uint32_t)ks * 32u;
            const uint32_t kB = (uint32_t)ks * 16u * PITCHB64 * 2u;
            uint32_t ah[2][4], al[2][4], bh[2][4], bl[2][4];
            LDMX4(ah[0], base + aoffH + kA);
            LDMX4(ah[1], base + aoffH + 16u * PITCHA * 2u + kA);
            LDMX4(al[0], base + aoffH + (AL64 - AH64) + kA);
            LDMX4(al[1], base + aoffH + (AL64 - AH64) + 16u * PITCHA * 2u + kA);
#pragma unroll
            for (int gp = 0; gp < 2; ++gp) {
                LDMX4T(bh[gp], base + boff + gp * 32u + kB);
                LDMX4T(bl[gp], base + boff + (BL64 - BH64) + gp * 32u + kB);
            }
#pragma unroll
            for (int mt = 0; mt < 2; ++mt)
#pragma unroll
                for (int nt = 0; nt < 4; ++nt) {
                    const int gp = nt >> 1, ix = (nt & 1) * 2;
                    MMA_BF16(acc[mt][nt], ah[mt], bh[gp][ix], bh[gp][ix + 1]);
                    MMA_BF16(acc[mt][nt], ah[mt], bl[gp][ix], bl[gp][ix + 1]);
                    MMA_BF16(acc[mt][nt], al[mt], bh[gp][ix], bh[gp][ix + 1]);
                }
        }
        if (t + 1 < T) STORE_STAGE((t + 1) & 1);
        if (t + 2 < T) LOADG(t + 2);
        __syncthreads();
    }
#undef LOADG
#undef STORE_STAGE

    const int g  = lid >> 2;
    const int tq = lid & 3;
#pragma unroll
    for (int mt = 0; mt < 2; ++mt) {
#pragma unroll
        for (int nt = 0; nt < 4; ++nt) {
            int col = n0 + ns * 32 + nt * 8 + tq * 2;
            float bc0 = 0.f, bc1 = 0.f;
            if (bias_mode == 1) { bc0 = bias[col]; bc1 = bias[col + 1]; }
#pragma unroll
            for (int half = 0; half < 2; ++half) {
                int m = ms * 32 + mt * 16 + g + half * 8;
                if (m >= Mreal) continue;
                float rb = (bias_mode == 2) ? bias[m] : 0.0f;
                float vx = acc[mt][nt][half * 2 + 0] + bc0 + rb;
                float vy = acc[mt][nt][half * 2 + 1] + bc1 + rb;
                if (do_relu) { vx = fmaxf(vx, 0.f); vy = fmaxf(vy, 0.f); }
                if (OSPL) {
                    uint32_t hw, lw;
                    split2(vx, vy, hw, lw);
                    size_t off = (size_t)m * ldc + col;
                    *(uint32_t*)(Ch + off) = hw;
                    *(uint32_t*)(Cl + off) = lw;
                } else {
                    *(float2*)&C[(size_t)m * ldc + col] = make_float2(vx, vy);
                }
            }
        }
    }
}

// ---------------------------------------------------------------------------
extern "C" void kernel_launch(void* const* d_in, const int* in_sizes, int n_in,
                              void* d_out, int out_size)
{
    const float* x   = (const float*)d_in[0];
    const int*   adj = (const int*)  d_in[1];
    const float* W2  = (const float*)d_in[2];
    const float* b2  = (const float*)d_in[3];
    const float* W1  = (const float*)d_in[4];
    const float* b1  = (const float*)d_in[5];
    const float* Wl  = (const float*)d_in[6];
    const float* bl  = (const float*)d_in[7];
    float* out = (float*)d_out;

    float *h, *out1, *Mn, *Wlp, *P;
    __nv_bfloat16 *xh, *xl, *hh, *hl, *ah, *al;
    cudaGetSymbolAddress((void**)&h,    g_h);
    cudaGetSymbolAddress((void**)&out1, g_out1);
    cudaGetSymbolAddress((void**)&Mn,   g_Mn);
    cudaGetSymbolAddress((void**)&Wlp,  g_Wlp);
    cudaGetSymbolAddress((void**)&P,    g_P);
    cudaGetSymbolAddress((void**)&xh, g_xh);  cudaGetSymbolAddress((void**)&xl, g_xl);
    cudaGetSymbolAddress((void**)&hh, g_hh);  cudaGetSymbolAddress((void**)&hl, g_hl);
    cudaGetSymbolAddress((void**)&ah, g_ah);  cudaGetSymbolAddress((void**)&al, g_al);

    cudaFuncSetAttribute(tgemmA, cudaFuncAttributeMaxDynamicSharedMemorySize, DSA);
    cudaFuncSetAttribute(tgemm64<0>, cudaFuncAttributeMaxDynamicSharedMemorySize, DS64);
    cudaFuncSetAttribute(tgemm64<1>, cudaFuncAttributeMaxDynamicSharedMemorySize, DS64);

    dim3 b(NTH);
    dim3 gBig(CC / BNT, 4);   // 32 x 4 = 128 CTAs
    dim3 gSm (CC / 64);       // 64 CTAs
    int cgrid = (NN * CC / 4 + 255) / 256;

    split_x_kernel<<<(NN * CC / 8 + 255) / 256, 256>>>(x);
    prep_kernel<<<NPAD, NPAD>>>(adj, Wl);

    // K1: P_s = x @ W2 (4 k-slices of 1024)
    tgemmA<<<gBig, b, DSA>>>(xh, xl, CC, CC, W2, CC,
                             nullptr, nullptr, 0, 0, nullptr, 0,
                             /*SPLITS=*/4, P, CC, NN);
    // h (fp32 + bf16 pairs) = sum P + b2
    combine_kernel<<<cgrid, 256>>>(P, b2, 0, h, hh, hl);

    // K2: aggr pairs = Mn @ h
    tgemm64<1><<<gSm, b, DS64>>>(Mn, NPAD, NPAD, h, CC,
                                 nullptr, 0, 0,
                                 nullptr, ah, al, CC, NN);

    // K3: P_s = h @ W1_top | aggr @ W1_bot (2 slices each)
    tgemmA<<<gBig, b, DSA>>>(hh, hl, CC, CC, W1, CC,
                             ah, al, CC, CC, W1 + (size_t)CC * CC, CC,
                             /*SPLITS=*/2, P, CC, NN);
    // out1 = relu(sum P + b1)
    combine_kernel<<<cgrid, 256>>>(P, b1, 1, out1, nullptr, nullptr);

    // K4: out = Wlp @ out1 + bl[:,None]
    tgemm64<0><<<gSm, b, DS64>>>(Wlp, NPAD, NPAD, out1, CC,
                                 bl, 2, 0,
                                 out, nullptr, nullptr, CC, NN);
}

// round 10
// speedup vs baseline: 1.0476x; 1.0476x over previous
#include <cuda_runtime.h>
#include <cuda_bf16.h>
#include <cstdint>

#define NN 110
#define CC 4096
#define NPAD 128

#define BM 128
#define BKC 64          // fp32 k per chunk
#define PITCHA 72       // bf16 elems per A smem row (64 + 8 pad)
#define NTH 256

#define PS (NPAD * CC)  // partial buffer stride

// -------------------- scratch (zero-initialized device globals) ------------
__device__ float g_h   [NPAD * CC];
__device__ float g_aggr[NPAD * CC];
__device__ float g_out1[NPAD * CC];
__device__ float g_Mn  [NPAD * NPAD];
__device__ float g_Wlp [NPAD * NPAD];
__device__ float g_P   [4 * PS];

// -------------------- helpers ----------------------------------------------
__device__ __forceinline__ uint32_t smem_u32(const void* p) {
    uint32_t a;
    asm("{ .reg .u64 t; cvta.to.shared.u64 t, %1; cvt.u32.u64 %0, t; }"
        : "=r"(a) : "l"(p));
    return a;
}

__device__ __forceinline__ void split2(float x0, float x1, uint32_t& hi, uint32_t& lo) {
    uint32_t h;
    asm("cvt.rn.bf16x2.f32 %0, %1, %2;" : "=r"(h) : "f"(x1), "f"(x0));
    float h0 = __uint_as_float(h << 16);
    float h1 = __uint_as_float(h & 0xFFFF0000u);
    float r0 = x0 - h0;
    float r1 = x1 - h1;
    asm("cvt.rn.bf16x2.f32 %0, %1, %2;" : "=r"(lo) : "f"(r1), "f"(r0));
    hi = h;
}

#define LDMX4(r, addr)                                                        \
    asm volatile("ldmatrix.sync.aligned.m8n8.x4.shared.b16 {%0,%1,%2,%3}, [%4];" \
        : "=r"((r)[0]), "=r"((r)[1]), "=r"((r)[2]), "=r"((r)[3]) : "r"(addr))

#define LDMX4T(r, addr)                                                       \
    asm volatile("ldmatrix.sync.aligned.m8n8.x4.trans.shared.b16 {%0,%1,%2,%3}, [%4];" \
        : "=r"((r)[0]), "=r"((r)[1]), "=r"((r)[2]), "=r"((r)[3]) : "r"(addr))

#define MMA_BF16(acc, a, b0, b1)                                              \
    asm volatile("mma.sync.aligned.m16n8k16.row.col.f32.bf16.bf16.f32 "       \
        "{%0,%1,%2,%3}, {%4,%5,%6,%7}, {%8,%9}, {%0,%1,%2,%3};"               \
        : "+f"((acc)[0]), "+f"((acc)[1]), "+f"((acc)[2]), "+f"((acc)[3])      \
        : "r"((a)[0]), "r"((a)[1]), "r"((a)[2]), "r"((a)[3]), "r"(b0), "r"(b1))

// ---------------------------------------------------------------------------
// Prep: Mn[j][i] = (adj[i][j]!=0)/max(deg_j,1); Wl padded to 128 (fp32).
// ---------------------------------------------------------------------------
__global__ void prep_kernel(const int* __restrict__ adj, const float* __restrict__ Wl) {
    const int j = blockIdx.x;
    const int i = threadIdx.x;
    __shared__ int sdeg[NPAD];
    int a = (i < NN && j < NN) ? (adj[i * NN + j] != 0) : 0;
    sdeg[i] = a;
    __syncthreads();
#pragma unroll
    for (int s = 64; s > 0; s >>= 1) {
        if (i < s) sdeg[i] += sdeg[i + s];
        __syncthreads();
    }
    const int deg = sdeg[0];
    const float inv = (j < NN) ? 1.0f / (float)(deg > 1 ? deg : 1) : 0.0f;
    g_Mn [j * NPAD + i] = a ? inv : 0.0f;
    g_Wlp[j * NPAD + i] = (i < NN && j < NN) ? Wl[j * NN + i] : 0.0f;
}

// ---------------------------------------------------------------------------
// Combine: out = act(sum_{s<4} P_s + bias_col)
// ---------------------------------------------------------------------------
__global__ void combine_kernel(const float* __restrict__ P,
                               const float* __restrict__ bias, int do_relu,
                               float* __restrict__ out) {
    int e = (blockIdx.x * blockDim.x + threadIdx.x) * 4;
    if (e >= NN * CC) return;
    float4 p0 = *(const float4*)(P + e);
    float4 p1 = *(const float4*)(P + PS + e);
    float4 p2 = *(const float4*)(P + 2 * PS + e);
    float4 p3 = *(const float4*)(P + 3 * PS + e);
    float4 bv = *(const float4*)(bias + (e & (CC - 1)));
    float4 v;
    v.x = (p0.x + p1.x) + (p2.x + p3.x) + bv.x;
    v.y = (p0.y + p1.y) + (p2.y + p3.y) + bv.y;
    v.z = (p0.z + p1.z) + (p2.z + p3.z) + bv.z;
    v.w = (p0.w + p1.w) + (p2.w + p3.w) + bv.w;
    if (do_relu) {
        v.x = fmaxf(v.x, 0.f); v.y = fmaxf(v.y, 0.f);
        v.z = fmaxf(v.z, 0.f); v.w = fmaxf(v.w, 0.f);
    }
    *(float4*)(out + e) = v;
}

// ---------------------------------------------------------------------------
// bf16-split HMMA GEMM. CTA tile 128 x BNT, 8 warps (4m x 2n),
// warp tile 32 x (BNT/2). blockIdx.y = slice; SPLITS slices per operand pair.
// Chunk tail (convert+STS, LDG prefetch) is software-pipelined into the
// 4 k-steps so it overlaps the tensor pipe.
// ---------------------------------------------------------------------------
template<int BNT>
__global__ __launch_bounds__(NTH, 1)
void tgemm(const float* __restrict__ A1, int lda1, int ka1,
           const float* __restrict__ B1, int ldb1,
           const float* __restrict__ A2, int lda2, int ka2,
           const float* __restrict__ B2, int ldb2,
           int SPLITS,
           const float* __restrict__ bias, int bias_mode, int do_relu,
           int partial,
           float* __restrict__ C, int ldc, int Mreal)
{
    constexpr int NTW = BNT / 16;            // n8-tiles per warp (warp spans BNT/2)
    constexpr int PITCHB = BNT + 8;          // bf16 elems per B smem row
    constexpr int NBG = NTW / 2;             // B ldmatrix groups per term
    constexpr int FB = BNT / 16;             // float4s per thread for B load
    constexpr uint32_t AH_OFF = 0;
    constexpr uint32_t AL_OFF = BM * PITCHA * 2;             // 18432
    constexpr uint32_t BH_OFF = 2 * BM * PITCHA * 2;         // 36864
    constexpr uint32_t BBYTES = (uint32_t)BKC * PITCHB * 2;
    constexpr uint32_t BL_OFF = BH_OFF + BBYTES;
    constexpr uint32_t STAGE  = BH_OFF + 2 * BBYTES;

    extern __shared__ __align__(16) char dsm[];
    const uint32_t sb = smem_u32(dsm);

    const int tid = threadIdx.x;
    const int wid = tid >> 5;
    const int lid = tid & 31;
    const int ms = wid & 3;                  // 4 m-warps, base ms*32
    const int ns = wid >> 2;                 // 2 n-warps, base ns*(BNT/2)
    const int n0 = blockIdx.x * BNT;
    const int slice = blockIdx.y;

    // slice -> operand pair + k window (constant per CTA)
    const int pair = slice / SPLITS;
    const int q    = slice % SPLITS;
    const float* A = pair ? A2 : A1;
    const float* B = pair ? B2 : B1;
    const int lda = pair ? lda2 : lda1;
    const int ldb = pair ? ldb2 : ldb1;
    const int kaeff = (pair ? ka2 : ka1) / SPLITS;
    const int kbase = q * kaeff;
    const int T = kaeff / BKC;

    // A loader: 128 rows x 64 k fp32, float4, 8 passes (16 threads/row)
    const int alrow = tid >> 4;
    const int alc   = (tid & 15) * 4;
    // B loader: 64 k x BNT n; thread -> (k row, BNT/4 n)
    const int bkq = tid >> 2;
    const int bnq = (tid & 3) * (BNT / 4);

    float acc[2][NTW][4];
#pragma unroll
    for (int a = 0; a < 2; ++a)
#pragma unroll
        for (int b = 0; b < NTW; ++b)
#pragma unroll
            for (int c = 0; c < 4; ++c) acc[a][b][c] = 0.0f;

    // A fragment lane offsets (validated non-trans layout)
    const uint32_t aoffH = AH_OFF +
        (((uint32_t)(ms * 32 + (lid & 15)) * PITCHA) + ((lid >> 4) & 1) * 8u) * 2u;
    // B fragment lane offsets (validated trans layout, [k][n] smem)
    const uint32_t boff = BH_OFF +
        (((uint32_t)(lid & 15) * PITCHB) + (uint32_t)(ns * (BNT / 2) + (lid >> 4) * 8)) * 2u;

    float4 fa[8];
    float4 fbr[FB];
    const float4 f4z = make_float4(0.f, 0.f, 0.f, 0.f);

#define LOADG(T_)                                                              \
    do {                                                                       \
        int k0_ = kbase + (T_) * BKC;                                          \
        _Pragma("unroll")                                                      \
        for (int p = 0; p < 8; ++p) {                                          \
            int m = p * 16 + alrow;                                            \
            fa[p] = (m < Mreal) ? *(const float4*)(A + (size_t)m * lda + k0_ + alc) : f4z; \
        }                                                                      \
        const float* p_ = B + (size_t)(k0_ + bkq) * ldb + n0 + bnq;            \
        _Pragma("unroll")                                                      \
        for (int j = 0; j < FB; ++j)                                           \
            fbr[j] = *(const float4*)(p_ + j * 4);                             \
    } while (0)

#define STORE_STAGE(bufsel)                                                    \
    do {                                                                       \
        char* st = dsm + (bufsel) * STAGE;                                     \
        _Pragma("unroll")                                                      \
        for (int p = 0; p < 8; ++p) {                                          \
            int row = p * 16 + alrow;                                          \
            uint32_t h0, l0, h1, l1;                                           \
            split2(fa[p].x, fa[p].y, h0, l0);                                  \
            split2(fa[p].z, fa[p].w, h1, l1);                                  \
            uint32_t off = ((uint32_t)row * PITCHA + (uint32_t)alc) * 2u;      \
            *(uint2*)(st + AH_OFF + off) = make_uint2(h0, h1);                 \
            *(uint2*)(st + AL_OFF + off) = make_uint2(l0, l1);                 \
        }                                                                      \
        {                                                                      \
            uint32_t o_ = ((uint32_t)bkq * PITCHB + (uint32_t)bnq) * 2u;       \
            _Pragma("unroll")                                                  \
            for (int j = 0; j < FB; j += 2) {                                  \
                uint4 hv, lv;                                                  \
                split2(fbr[j].x,     fbr[j].y,     hv.x, lv.x);                \
                split2(fbr[j].z,     fbr[j].w,     hv.y, lv.y);                \
                split2(fbr[j + 1].x, fbr[j + 1].y, hv.z, lv.z);                \
                split2(fbr[j + 1].z, fbr[j + 1].w, hv.w, lv.w);                \
                *(uint4*)(st + BH_OFF + o_ + j * 8) = hv;                      \
                *(uint4*)(st + BL_OFF + o_ + j * 8) = lv;                      \
            }                                                                  \
        }                                                                      \
    } while (0)

    // quarter store: fa[2q..2q+1] and (if in range) fbr[2q..2q+1]
#define STORE_Q(bufsel, q_)                                                    \
    do {                                                                       \
        char* st = dsm + (bufsel) * STAGE;                                     \
        _Pragma("unroll")                                                      \
        for (int p = 2 * (q_); p < 2 * (q_) + 2; ++p) {                        \
            int row = p * 16 + alrow;                                          \
            uint32_t h0, l0, h1, l1;                                           \
            split2(fa[p].x, fa[p].y, h0, l0);                                  \
            split2(fa[p].z, fa[p].w, h1, l1);                                  \
            uint32_t off = ((uint32_t)row * PITCHA + (uint32_t)alc) * 2u;      \
            *(uint2*)(st + AH_OFF + off) = make_uint2(h0, h1);                 \
            *(uint2*)(st + AL_OFF + off) = make_uint2(l0, l1);                 \
        }                                                                      \
        if (2 * (q_) < FB) {                                                   \
            const int j = 2 * (q_);                                            \
            uint4 hv, lv;                                                      \
            split2(fbr[j].x,     fbr[j].y,     hv.x, lv.x);                    \
            split2(fbr[j].z,     fbr[j].w,     hv.y, lv.y);                    \
            split2(fbr[j + 1].x, fbr[j + 1].y, hv.z, lv.z);                    \
            split2(fbr[j + 1].z, fbr[j + 1].w, hv.w, lv.w);                    \
            uint32_t o_ = ((uint32_t)bkq * PITCHB + (uint32_t)bnq) * 2u;       \
            *(uint4*)(st + BH_OFF + o_ + j * 8) = hv;                          \
            *(uint4*)(st + BL_OFF + o_ + j * 8) = lv;                          \
        }                                                                      \
    } while (0)

    // quarter load: fa[2q..2q+1] and (if in range) fbr[2q..2q+1]
#define LOAD_Q(T_, q_)                                                         \
    do {                                                                       \
        int k0_ = kbase + (T_) * BKC;                                          \
        _Pragma("unroll")                                                      \
        for (int p = 2 * (q_); p < 2 * (q_) + 2; ++p) {                        \
            int m = p * 16 + alrow;                                            \
            fa[p] = (m < Mreal) ? *(const float4*)(A + (size_t)m * lda + k0_ + alc) : f4z; \
        }                                                                      \
        if (2 * (q_) < FB) {                                                   \
            const int j = 2 * (q_);                                            \
            const float* p_ = B + (size_t)(k0_ + bkq) * ldb + n0 + bnq;        \
            fbr[j]     = *(const float4*)(p_ + j * 4);                         \
            fbr[j + 1] = *(const float4*)(p_ + j * 4 + 4);                     \
        }                                                                      \
    } while (0)

    // ---- prologue ----
    LOADG(0);
    STORE_STAGE(0);
    if (T > 1) LOADG(1);
    __syncthreads();

    for (int t = 0; t < T; ++t) {
        const uint32_t base = sb + (uint32_t)(t & 1) * STAGE;
        const int doStore = (t + 1 < T);
        const int doLoad  = (t + 2 < T);

        // ---- 4 k-steps of 16, with tail quarters interleaved ----
#pragma unroll
        for (int ks = 0; ks < 4; ++ks) {
            const uint32_t kA = (uint32_t)ks * 32u;
            const uint32_t kB = (uint32_t)ks * 16u * PITCHB * 2u;
            uint32_t ah[2][4], al[2][4], bh[NBG][4], bl[NBG][4];
            LDMX4(ah[0], base + aoffH + kA);
            LDMX4(ah[1], base + aoffH + 16u * PITCHA * 2u + kA);
            LDMX4(al[0], base + aoffH + (AL_OFF - AH_OFF) + kA);
            LDMX4(al[1], base + aoffH + (AL_OFF - AH_OFF) + 16u * PITCHA * 2u + kA);
#pragma unroll
            for (int gp = 0; gp < NBG; ++gp) {
                LDMX4T(bh[gp], base + boff + gp * 32u + kB);
                LDMX4T(bl[gp], base + boff + (BL_OFF - BH_OFF) + gp * 32u + kB);
            }
#pragma unroll
            for (int mt = 0; mt < 2; ++mt)
#pragma unroll
                for (int nt = 0; nt < NTW; ++nt) {
                    const int gp = nt >> 1, ix = (nt & 1) * 2;
                    MMA_BF16(acc[mt][nt], ah[mt], bh[gp][ix], bh[gp][ix + 1]);
                    MMA_BF16(acc[mt][nt], ah[mt], bl[gp][ix], bl[gp][ix + 1]);
                    MMA_BF16(acc[mt][nt], al[mt], bh[gp][ix], bh[gp][ix + 1]);
                }

            // tail quarter: store stage(t+1) piece, then refill regs for t+2
            if (doStore) STORE_Q((t + 1) & 1, ks);
            if (doLoad)  LOAD_Q(t + 2, ks);
        }

        __syncthreads();
    }
#undef LOADG
#undef STORE_STAGE
#undef STORE_Q
#undef LOAD_Q

    // ---- epilogue ----
    const int g  = lid >> 2;
    const int tq = lid & 3;
    float* Pout = C + (size_t)slice * PS;
#pragma unroll
    for (int mt = 0; mt < 2; ++mt) {
#pragma unroll
        for (int nt = 0; nt < NTW; ++nt) {
            int col = n0 + ns * (BNT / 2) + nt * 8 + tq * 2;
            float bc0 = 0.f, bc1 = 0.f;
            if (!partial && bias_mode == 1) { bc0 = bias[col]; bc1 = bias[col + 1]; }
#pragma unroll
            for (int half = 0; half < 2; ++half) {
                int m = ms * 32 + mt * 16 + g + half * 8;
                if (m >= Mreal) continue;
                float vx = acc[mt][nt][half * 2 + 0];
                float vy = acc[mt][nt][half * 2 + 1];
                if (partial) {
                    *(float2*)&Pout[(size_t)m * ldc + col] = make_float2(vx, vy);
                } else {
                    float rb = (bias_mode == 2) ? bias[m] : 0.0f;
                    vx += bc0 + rb;
                    vy += bc1 + rb;
                    if (do_relu) { vx = fmaxf(vx, 0.f); vy = fmaxf(vy, 0.f); }
                    *(float2*)&C[(size_t)m * ldc + col] = make_float2(vx, vy);
                }
            }
        }
    }
}

// ---------------------------------------------------------------------------
extern "C" void kernel_launch(void* const* d_in, const int* in_sizes, int n_in,
                              void* d_out, int out_size)
{
    const float* x   = (const float*)d_in[0];
    const int*   adj = (const int*)  d_in[1];
    const float* W2  = (const float*)d_in[2];
    const float* b2  = (const float*)d_in[3];
    const float* W1  = (const float*)d_in[4];
    const float* b1  = (const float*)d_in[5];
    const float* Wl  = (const float*)d_in[6];
    const float* bl  = (const float*)d_in[7];
    float* out = (float*)d_out;

    float *h, *aggr, *out1, *Mn, *Wlp, *P;
    cudaGetSymbolAddress((void**)&h,    g_h);
    cudaGetSymbolAddress((void**)&aggr, g_aggr);
    cudaGetSymbolAddress((void**)&out1, g_out1);
    cudaGetSymbolAddress((void**)&Mn,   g_Mn);
    cudaGetSymbolAddress((void**)&Wlp,  g_Wlp);
    cudaGetSymbolAddress((void**)&P,    g_P);

    // dynamic smem sizes
    const int DS64  = 2 * (2 * BM * PITCHA * 2 + 2 * BKC * (64 + 8) * 2);    // 110592
    const int DS128 = 2 * (2 * BM * PITCHA * 2 + 2 * BKC * (128 + 8) * 2);   // 143360
    cudaFuncSetAttribute(tgemm<64>,  cudaFuncAttributeMaxDynamicSharedMemorySize, DS64);
    cudaFuncSetAttribute(tgemm<128>, cudaFuncAttributeMaxDynamicSharedMemorySize, DS128);

    dim3 b(NTH);
    dim3 gBig(CC / 128, 4);   // 32 x 4 slices = 128 CTAs
    dim3 gSm (CC / 64, 1);    // 64 CTAs
    int cgrid = (NN * CC / 4 + 255) / 256;

    prep_kernel<<<NPAD, NPAD>>>(adj, Wl);

    // K1: P_s = x @ W2 over k slices of 1024 (s=0..3)
    tgemm<128><<<gBig, b, DS128>>>(x, CC, CC, W2, CC,
                                   nullptr, 0, 0, nullptr, 0,
                                   /*SPLITS=*/4,
                                   nullptr, 0, 0, /*partial=*/1,
                                   P, CC, NN);
    combine_kernel<<<cgrid, 256>>>(P, b2, 0, h);

    // K2: aggr = Mn @ h (direct)
    tgemm<64><<<gSm, b, DS64>>>(Mn, NPAD, NPAD, h, CC,
                                nullptr, 0, 0, nullptr, 0,
                                /*SPLITS=*/1,
                                nullptr, 0, 0, /*partial=*/0,
                                aggr, CC, NN);

    // K3: P_s = (h @ W1_top | aggr @ W1_bot), each pair split in 2 (s=0..3)
    tgemm<128><<<gBig, b, DS128>>>(h, CC, CC, W1, CC,
                                   aggr, CC, CC, W1 + (size_t)CC * CC, CC,
                                   /*SPLITS=*/2,
                                   nullptr, 0, 0, /*partial=*/1,
                                   P, CC, NN);
    combine_kernel<<<cgrid, 256>>>(P, b1, 1, out1);

    // K4: out = Wlp @ out1 + bl[:,None] (direct)
    tgemm<64><<<gSm, b, DS64>>>(Wlp, NPAD, NPAD, out1, CC,
                                nullptr, 0, 0, nullptr, 0,
                                /*SPLITS=*/1,
                                bl, 2, 0, /*partial=*/0,
                                out, CC, NN);
}

// round 11
// speedup vs baseline: 1.1735x; 1.1201x over previous
#include <cuda_runtime.h>
#include <cuda_bf16.h>
#include <cstdint>

#define NN 110
#define CC 4096
#define NPAD 128

#define BM 128
#define BKC 64          // fp32 k per chunk
#define PITCHA 72       // bf16 elems per A smem row (64 + 8 pad)

#define PS (NPAD * CC)  // partial buffer stride

// -------------------- scratch (zero-initialized device globals) ------------
__device__ float g_h   [NPAD * CC];
__device__ float g_aggr[NPAD * CC];
__device__ float g_out1[NPAD * CC];
__device__ float g_Mn  [NPAD * NPAD];
__device__ float g_Wlp [NPAD * NPAD];
__device__ float g_P   [4 * PS];

// -------------------- helpers ----------------------------------------------
__device__ __forceinline__ uint32_t smem_u32(const void* p) {
    uint32_t a;
    asm("{ .reg .u64 t; cvta.to.shared.u64 t, %1; cvt.u32.u64 %0, t; }"
        : "=r"(a) : "l"(p));
    return a;
}

__device__ __forceinline__ void split2(float x0, float x1, uint32_t& hi, uint32_t& lo) {
    uint32_t h;
    asm("cvt.rn.bf16x2.f32 %0, %1, %2;" : "=r"(h) : "f"(x1), "f"(x0));
    float h0 = __uint_as_float(h << 16);
    float h1 = __uint_as_float(h & 0xFFFF0000u);
    float r0 = x0 - h0;
    float r1 = x1 - h1;
    asm("cvt.rn.bf16x2.f32 %0, %1, %2;" : "=r"(lo) : "f"(r1), "f"(r0));
    hi = h;
}

#define LDMX4(r, addr)                                                        \
    asm volatile("ldmatrix.sync.aligned.m8n8.x4.shared.b16 {%0,%1,%2,%3}, [%4];" \
        : "=r"((r)[0]), "=r"((r)[1]), "=r"((r)[2]), "=r"((r)[3]) : "r"(addr))

#define LDMX4T(r, addr)                                                       \
    asm volatile("ldmatrix.sync.aligned.m8n8.x4.trans.shared.b16 {%0,%1,%2,%3}, [%4];" \
        : "=r"((r)[0]), "=r"((r)[1]), "=r"((r)[2]), "=r"((r)[3]) : "r"(addr))

#define MMA_BF16(acc, a, b0, b1)                                              \
    asm volatile("mma.sync.aligned.m16n8k16.row.col.f32.bf16.bf16.f32 "       \
        "{%0,%1,%2,%3}, {%4,%5,%6,%7}, {%8,%9}, {%0,%1,%2,%3};"               \
        : "+f"((acc)[0]), "+f"((acc)[1]), "+f"((acc)[2]), "+f"((acc)[3])      \
        : "r"((a)[0]), "r"((a)[1]), "r"((a)[2]), "r"((a)[3]), "r"(b0), "r"(b1))

// ---------------------------------------------------------------------------
// Prep: Mn[j][i] = (adj[i][j]!=0)/max(deg_j,1); Wl padded to 128 (fp32).
// ---------------------------------------------------------------------------
__global__ void prep_kernel(const int* __restrict__ adj, const float* __restrict__ Wl) {
    const int j = blockIdx.x;
    const int i = threadIdx.x;
    __shared__ int sdeg[NPAD];
    int a = (i < NN && j < NN) ? (adj[i * NN + j] != 0) : 0;
    sdeg[i] = a;
    __syncthreads();
#pragma unroll
    for (int s = 64; s > 0; s >>= 1) {
        if (i < s) sdeg[i] += sdeg[i + s];
        __syncthreads();
    }
    const int deg = sdeg[0];
    const float inv = (j < NN) ? 1.0f / (float)(deg > 1 ? deg : 1) : 0.0f;
    g_Mn [j * NPAD + i] = a ? inv : 0.0f;
    g_Wlp[j * NPAD + i] = (i < NN && j < NN) ? Wl[j * NN + i] : 0.0f;
}

// ---------------------------------------------------------------------------
// Combine: out = act(sum_{s<4} P_s + bias_col)
// ---------------------------------------------------------------------------
__global__ void combine_kernel(const float* __restrict__ P,
                               const float* __restrict__ bias, int do_relu,
                               float* __restrict__ out) {
    int e = (blockIdx.x * blockDim.x + threadIdx.x) * 4;
    if (e >= NN * CC) return;
    float4 p0 = *(const float4*)(P + e);
    float4 p1 = *(const float4*)(P + PS + e);
    float4 p2 = *(const float4*)(P + 2 * PS + e);
    float4 p3 = *(const float4*)(P + 3 * PS + e);
    float4 bv = *(const float4*)(bias + (e & (CC - 1)));
    float4 v;
    v.x = (p0.x + p1.x) + (p2.x + p3.x) + bv.x;
    v.y = (p0.y + p1.y) + (p2.y + p3.y) + bv.y;
    v.z = (p0.z + p1.z) + (p2.z + p3.z) + bv.z;
    v.w = (p0.w + p1.w) + (p2.w + p3.w) + bv.w;
    if (do_relu) {
        v.x = fmaxf(v.x, 0.f); v.y = fmaxf(v.y, 0.f);
        v.z = fmaxf(v.z, 0.f); v.w = fmaxf(v.w, 0.f);
    }
    *(float4*)(out + e) = v;
}

// ===========================================================================
// tgemm512: CTA tile 128x128, 512 threads, 16 warps (4m x 4n), warp tile
// 32x32. Double-buffered smem, one sync per chunk (R8 pipeline shape).
// Always writes fp32 partials to C + slice*PS (big GEMMs only).
// ===========================================================================
#define BNT 128
#define PITCHB (BNT + 8)
#define AH_OFF 0u
#define AL_OFF ((uint32_t)BM * PITCHA * 2u)            // 18432
#define BH_OFF (2u * AL_OFF)                           // 36864
#define BBYTES ((uint32_t)BKC * PITCHB * 2u)           // 17408
#define BL_OFF (BH_OFF + BBYTES)
#define STAGE  (BH_OFF + 2u * BBYTES)                  // 71680
#define DS512  (2u * STAGE)                            // 143360

__global__ __launch_bounds__(512, 1)
void tgemm512(const float* __restrict__ A1, int lda1, int ka1,
              const float* __restrict__ B1, int ldb1,
              const float* __restrict__ A2, int lda2, int ka2,
              const float* __restrict__ B2, int ldb2,
              int SPLITS,
              float* __restrict__ C, int ldc, int Mreal)
{
    extern __shared__ __align__(16) char dsm[];
    const uint32_t sb = smem_u32(dsm);

    const int tid = threadIdx.x;
    const int wid = tid >> 5;
    const int lid = tid & 31;
    const int ms = wid & 3;                  // 4 m-warps, base ms*32
    const int ns = wid >> 2;                 // 4 n-warps, base ns*32
    const int n0 = blockIdx.x * BNT;
    const int slice = blockIdx.y;

    const int pair = slice / SPLITS;
    const int q    = slice % SPLITS;
    const float* A = pair ? A2 : A1;
    const float* B = pair ? B2 : B1;
    const int lda = pair ? lda2 : lda1;
    const int ldb = pair ? ldb2 : ldb1;
    const int kaeff = (pair ? ka2 : ka1) / SPLITS;
    const int kbase = q * kaeff;
    const int T = kaeff / BKC;

    // A loader: 128 rows x 64 k fp32; 4 threads/row, 16 floats each
    const int alrow = tid >> 2;              // 0..127
    const int alc   = (tid & 3) * 16;        // col base (floats)
    // B loader: 64 k x 128 n; 8 threads/row, 16 floats each
    const int bkq = tid >> 3;                // 0..63
    const int bnq = (tid & 7) * 16;

    float acc[2][4][4];
#pragma unroll
    for (int a = 0; a < 2; ++a)
#pragma unroll
        for (int b = 0; b < 4; ++b)
#pragma unroll
            for (int c = 0; c < 4; ++c) acc[a][b][c] = 0.0f;

    // fragment lane offsets (validated layouts)
    const uint32_t aoffH = AH_OFF +
        (((uint32_t)(ms * 32 + (lid & 15)) * PITCHA) + ((lid >> 4) & 1) * 8u) * 2u;
    const uint32_t boff = BH_OFF +
        (((uint32_t)(lid & 15) * PITCHB) + (uint32_t)(ns * 32 + (lid >> 4) * 8)) * 2u;

    float4 fa[4];
    float4 fbr[4];
    const float4 f4z = make_float4(0.f, 0.f, 0.f, 0.f);
    const bool aok = (alrow < Mreal);

#define LOADG(T_)                                                              \
    do {                                                                       \
        int k0_ = kbase + (T_) * BKC;                                          \
        const float* pa_ = A + (size_t)alrow * lda + k0_ + alc;                \
        _Pragma("unroll")                                                      \
        for (int j = 0; j < 4; ++j)                                            \
            fa[j] = aok ? *(const float4*)(pa_ + j * 4) : f4z;                 \
        const float* pb_ = B + (size_t)(k0_ + bkq) * ldb + n0 + bnq;           \
        _Pragma("unroll")                                                      \
        for (int j = 0; j < 4; ++j)                                            \
            fbr[j] = *(const float4*)(pb_ + j * 4);                            \
    } while (0)

#define STORE_STAGE(bufsel)                                                    \
    do {                                                                       \
        char* st = dsm + (bufsel) * STAGE;                                     \
        {                                                                      \
            uint32_t oA_ = ((uint32_t)alrow * PITCHA + (uint32_t)alc) * 2u;    \
            _Pragma("unroll")                                                  \
            for (int j = 0; j < 4; j += 2) {                                   \
                uint4 hv, lv;                                                  \
                split2(fa[j].x,     fa[j].y,     hv.x, lv.x);                  \
                split2(fa[j].z,     fa[j].w,     hv.y, lv.y);                  \
                split2(fa[j + 1].x, fa[j + 1].y, hv.z, lv.z);                  \
                split2(fa[j + 1].z, fa[j + 1].w, hv.w, lv.w);                  \
                *(uint4*)(st + AH_OFF + oA_ + j * 8) = hv;                     \
                *(uint4*)(st + AL_OFF + oA_ + j * 8) = lv;                     \
            }                                                                  \
        }                                                                      \
        {                                                                      \
            uint32_t oB_ = ((uint32_t)bkq * PITCHB + (uint32_t)bnq) * 2u;      \
            _Pragma("unroll")                                                  \
            for (int j = 0; j < 4; j += 2) {                                   \
                uint4 hv, lv;                                                  \
                split2(fbr[j].x,     fbr[j].y,     hv.x, lv.x);                \
                split2(fbr[j].z,     fbr[j].w,     hv.y, lv.y);                \
                split2(fbr[j + 1].x, fbr[j + 1].y, hv.z, lv.z);                \
                split2(fbr[j + 1].z, fbr[j + 1].w, hv.w, lv.w);                \
                *(uint4*)(st + BH_OFF + oB_ + j * 8) = hv;                     \
                *(uint4*)(st + BL_OFF + oB_ + j * 8) = lv;                     \
            }                                                                  \
        }                                                                      \
    } while (0)

    // ---- prologue ----
    LOADG(0);
    STORE_STAGE(0);
    if (T > 1) LOADG(1);
    __syncthreads();

    for (int t = 0; t < T; ++t) {
        const uint32_t base = sb + (uint32_t)(t & 1) * STAGE;

        // ---- 4 k-steps of 16 ----
#pragma unroll
        for (int ks = 0; ks < 4; ++ks) {
            const uint32_t kA = (uint32_t)ks * 32u;
            const uint32_t kB = (uint32_t)ks * 16u * PITCHB * 2u;
            uint32_t ah[2][4], al[2][4], bh[2][4], bl[2][4];
            LDMX4(ah[0], base + aoffH + kA);
            LDMX4(ah[1], base + aoffH + 16u * PITCHA * 2u + kA);
            LDMX4(al[0], base + aoffH + (AL_OFF - AH_OFF) + kA);
            LDMX4(al[1], base + aoffH + (AL_OFF - AH_OFF) + 16u * PITCHA * 2u + kA);
#pragma unroll
            for (int gp = 0; gp < 2; ++gp) {
                LDMX4T(bh[gp], base + boff + gp * 32u + kB);
                LDMX4T(bl[gp], base + boff + (BL_OFF - BH_OFF) + gp * 32u + kB);
            }
#pragma unroll
            for (int mt = 0; mt < 2; ++mt)
#pragma unroll
                for (int nt = 0; nt < 4; ++nt) {
                    const int gp = nt >> 1, ix = (nt & 1) * 2;
                    MMA_BF16(acc[mt][nt], ah[mt], bh[gp][ix], bh[gp][ix + 1]);
                    MMA_BF16(acc[mt][nt], ah[mt], bl[gp][ix], bl[gp][ix + 1]);
                    MMA_BF16(acc[mt][nt], al[mt], bh[gp][ix], bh[gp][ix + 1]);
                }
        }

        // ---- stage t+1, prefetch t+2 ----
        if (t + 1 < T) STORE_STAGE((t + 1) & 1);
        if (t + 2 < T) LOADG(t + 2);

        __syncthreads();
    }
#undef LOADG
#undef STORE_STAGE

    // ---- epilogue: fp32 partials ----
    const int g  = lid >> 2;
    const int tq = lid & 3;
    float* Pout = C + (size_t)slice * PS;
#pragma unroll
    for (int mt = 0; mt < 2; ++mt) {
#pragma unroll
        for (int nt = 0; nt < 4; ++nt) {
            int col = n0 + ns * 32 + nt * 8 + tq * 2;
#pragma unroll
            for (int half = 0; half < 2; ++half) {
                int m = ms * 32 + mt * 16 + g + half * 8;
                if (m >= Mreal) continue;
                *(float2*)&Pout[(size_t)m * ldc + col] =
                    make_float2(acc[mt][nt][half * 2 + 0], acc[mt][nt][half * 2 + 1]);
            }
        }
    }
}

// ===========================================================================
// tgemm64: R8-proven 256-thread kernel, CTA tile 128x64 (K2/K4).
// ===========================================================================
#define PITCHB64 72
#define AH64 0u
#define AL64 18432u
#define BH64 36864u
#define BB64 ((uint32_t)BKC * PITCHB64 * 2u)   // 9216
#define BL64 (BH64 + BB64)
#define ST64 (BH64 + 2u * BB64)                // 55296
#define DS64 (2u * ST64)

__global__ __launch_bounds__(256, 1)
void tgemm64(const float* __restrict__ A1, int lda1, int ka1,
             const float* __restrict__ B1, int ldb1,
             const float* __restrict__ bias, int bias_mode, int do_relu,
             float* __restrict__ C, int ldc, int Mreal)
{
    extern __shared__ __align__(16) char dsm[];
    const uint32_t sb = smem_u32(dsm);

    const int tid = threadIdx.x;
    const int wid = tid >> 5;
    const int lid = tid & 31;
    const int ms = wid & 3;
    const int ns = wid >> 2;
    const int n0 = blockIdx.x * 64;

    const int T = ka1 / BKC;

    const int alrow = tid >> 4;
    const int alc   = (tid & 15) * 4;
    const int bkq = tid >> 2;
    const int bnq = (tid & 3) * 16;

    float acc[2][4][4];
#pragma unroll
    for (int a = 0; a < 2; ++a)
#pragma unroll
        for (int b = 0; b < 4; ++b)
#pragma unroll
            for (int c = 0; c < 4; ++c) acc[a][b][c] = 0.0f;

    const uint32_t aoffH = AH64 +
        (((uint32_t)(ms * 32 + (lid & 15)) * PITCHA) + ((lid >> 4) & 1) * 8u) * 2u;
    const uint32_t boff = BH64 +
        (((uint32_t)(lid & 15) * PITCHB64) + (uint32_t)(ns * 32 + (lid >> 4) * 8)) * 2u;

    float4 fa[8];
    float4 fbr[4];
    const float4 f4z = make_float4(0.f, 0.f, 0.f, 0.f);

#define LOADG(T_)                                                              \
    do {                                                                       \
        int k0_ = (T_) * BKC;                                                  \
        _Pragma("unroll")                                                      \
        for (int p = 0; p < 8; ++p) {                                          \
            int m = p * 16 + alrow;                                            \
            fa[p] = (m < Mreal) ? *(const float4*)(A1 + (size_t)m * lda1 + k0_ + alc) : f4z; \
        }                                                                      \
        const float* p_ = B1 + (size_t)(k0_ + bkq) * ldb1 + n0 + bnq;          \
        _Pragma("unroll")                                                      \
        for (int j = 0; j < 4; ++j)                                            \
            fbr[j] = *(const float4*)(p_ + j * 4);                             \
    } while (0)

#define STORE_STAGE(bufsel)                                                    \
    do {                                                                       \
        char* st = dsm + (bufsel) * ST64;                                      \
        _Pragma("unroll")                                                      \
        for (int p = 0; p < 8; ++p) {                                          \
            int row = p * 16 + alrow;                                          \
            uint32_t h0, l0, h1, l1;                                           \
            split2(fa[p].x, fa[p].y, h0, l0);                                  \
            split2(fa[p].z, fa[p].w, h1, l1);                                  \
            uint32_t off = ((uint32_t)row * PITCHA + (uint32_t)alc) * 2u;      \
            *(uint2*)(st + AH64 + off) = make_uint2(h0, h1);                   \
            *(uint2*)(st + AL64 + off) = make_uint2(l0, l1);                   \
        }                                                                      \
        {                                                                      \
            uint32_t o_ = ((uint32_t)bkq * PITCHB64 + (uint32_t)bnq) * 2u;     \
            _Pragma("unroll")                                                  \
            for (int j = 0; j < 4; j += 2) {                                   \
                uint4 hv, lv;                                                  \
                split2(fbr[j].x,     fbr[j].y,     hv.x, lv.x);                \
                split2(fbr[j].z,     fbr[j].w,     hv.y, lv.y);                \
                split2(fbr[j + 1].x, fbr[j + 1].y, hv.z, lv.z);                \
                split2(fbr[j + 1].z, fbr[j + 1].w, hv.w, lv.w);                \
                *(uint4*)(st + BH64 + o_ + j * 8u) = hv;                       \
                *(uint4*)(st + BL64 + o_ + j * 8u) = lv;                       \
            }                                                                  \
        }                                                                      \
    } while (0)

    LOADG(0);
    STORE_STAGE(0);
    if (T > 1) LOADG(1);
    __syncthreads();

    for (int t = 0; t < T; ++t) {
        const uint32_t base = sb + (uint32_t)(t & 1) * ST64;
#pragma unroll
        for (int ks = 0; ks < 4; ++ks) {
            const uint32_t kA = (uint32_t)ks * 32u;
            const uint32_t kB = (uint32_t)ks * 16u * PITCHB64 * 2u;
            uint32_t ah[2][4], al[2][4], bh[2][4], bl[2][4];
            LDMX4(ah[0], base + aoffH + kA);
            LDMX4(ah[1], base + aoffH + 16u * PITCHA * 2u + kA);
            LDMX4(al[0], base + aoffH + (AL64 - AH64) + kA);
            LDMX4(al[1], base + aoffH + (AL64 - AH64) + 16u * PITCHA * 2u + kA);
#pragma unroll
            for (int gp = 0; gp < 2; ++gp) {
                LDMX4T(bh[gp], base + boff + gp * 32u + kB);
                LDMX4T(bl[gp], base + boff + (BL64 - BH64) + gp * 32u + kB);
            }
#pragma unroll
            for (int mt = 0; mt < 2; ++mt)
#pragma unroll
                for (int nt = 0; nt < 4; ++nt) {
                    const int gp = nt >> 1, ix = (nt & 1) * 2;
                    MMA_BF16(acc[mt][nt], ah[mt], bh[gp][ix], bh[gp][ix + 1]);
                    MMA_BF16(acc[mt][nt], ah[mt], bl[gp][ix], bl[gp][ix + 1]);
                    MMA_BF16(acc[mt][nt], al[mt], bh[gp][ix], bh[gp][ix + 1]);
                }
        }
        if (t + 1 < T) STORE_STAGE((t + 1) & 1);
        if (t + 2 < T) LOADG(t + 2);
        __syncthreads();
    }
#undef LOADG
#undef STORE_STAGE

    const int g  = lid >> 2;
    const int tq = lid & 3;
#pragma unroll
    for (int mt = 0; mt < 2; ++mt) {
#pragma unroll
        for (int nt = 0; nt < 4; ++nt) {
            int col = n0 + ns * 32 + nt * 8 + tq * 2;
            float bc0 = 0.f, bc1 = 0.f;
            if (bias_mode == 1) { bc0 = bias[col]; bc1 = bias[col + 1]; }
#pragma unroll
            for (int half = 0; half < 2; ++half) {
                int m = ms * 32 + mt * 16 + g + half * 8;
                if (m >= Mreal) continue;
                float rb = (bias_mode == 2) ? bias[m] : 0.0f;
                float vx = acc[mt][nt][half * 2 + 0] + bc0 + rb;
                float vy = acc[mt][nt][half * 2 + 1] + bc1 + rb;
                if (do_relu) { vx = fmaxf(vx, 0.f); vy = fmaxf(vy, 0.f); }
                *(float2*)&C[(size_t)m * ldc + col] = make_float2(vx, vy);
            }
        }
    }
}

// ---------------------------------------------------------------------------
extern "C" void kernel_launch(void* const* d_in, const int* in_sizes, int n_in,
                              void* d_out, int out_size)
{
    const float* x   = (const float*)d_in[0];
    const int*   adj = (const int*)  d_in[1];
    const float* W2  = (const float*)d_in[2];
    const float* b2  = (const float*)d_in[3];
    const float* W1  = (const float*)d_in[4];
    const float* b1  = (const float*)d_in[5];
    const float* Wl  = (const float*)d_in[6];
    const float* bl  = (const float*)d_in[7];
    float* out = (float*)d_out;

    float *h, *aggr, *out1, *Mn, *Wlp, *P;
    cudaGetSymbolAddress((void**)&h,    g_h);
    cudaGetSymbolAddress((void**)&aggr, g_aggr);
    cudaGetSymbolAddress((void**)&out1, g_out1);
    cudaGetSymbolAddress((void**)&Mn,   g_Mn);
    cudaGetSymbolAddress((void**)&Wlp,  g_Wlp);
    cudaGetSymbolAddress((void**)&P,    g_P);

    cudaFuncSetAttribute(tgemm512, cudaFuncAttributeMaxDynamicSharedMemorySize, DS512);
    cudaFuncSetAttribute(tgemm64,  cudaFuncAttributeMaxDynamicSharedMemorySize, DS64);

    dim3 gBig(CC / BNT, 4);   // 32 x 4 slices = 128 CTAs (512 thr each)
    dim3 gSm (CC / 64, 1);    // 64 CTAs (256 thr each)
    int cgrid = (NN * CC / 4 + 255) / 256;

    prep_kernel<<<NPAD, NPAD>>>(adj, Wl);

    // K1: P_s = x @ W2 over 4 k-slices of 1024
    tgemm512<<<gBig, 512, DS512>>>(x, CC, CC, W2, CC,
                                   nullptr, 0, 0, nullptr, 0,
                                   /*SPLITS=*/4, P, CC, NN);
    combine_kernel<<<cgrid, 256>>>(P, b2, 0, h);

    // K2: aggr = Mn @ h (direct)
    tgemm64<<<gSm, 256, DS64>>>(Mn, NPAD, NPAD, h, CC,
                                nullptr, 0, 0, aggr, CC, NN);

    // K3: P_s = (h @ W1_top | aggr @ W1_bot), each split in 2
    tgemm512<<<gBig, 512, DS512>>>(h, CC, CC, W1, CC,
                                   aggr, CC, CC, W1 + (size_t)CC * CC, CC,
                                   /*SPLITS=*/2, P, CC, NN);
    combine_kernel<<<cgrid, 256>>>(P, b1, 1, out1);

    // K4: out = Wlp @ out1 + bl[:,None] (direct)
    tgemm64<<<gSm, 256, DS64>>>(Wlp, NPAD, NPAD, out1, CC,
                                bl, 2, 0, out, CC, NN);
}

// round 12
// speedup vs baseline: 1.2367x; 1.0539x over previous
#include <cuda_runtime.h>
#include <cuda_bf16.h>
#include <cstdint>

#define NN 110
#define CC 4096
#define NPAD 128

#define BM 128
#define BKC 64          // fp32 k per chunk
#define PITCHA 72       // bf16 elems per A smem row (64 + 8 pad)
#define NTH 256

#define PS (NPAD * CC)  // partial buffer stride

// -------------------- scratch (zero-initialized device globals) ------------
__device__ float g_h   [NPAD * CC];
__device__ float g_aggr[NPAD * CC];
__device__ float g_Mn  [NPAD * NPAD];
__device__ float g_Wlp [NPAD * NPAD];
__device__ float g_P   [4 * PS];

// -------------------- helpers ----------------------------------------------
__device__ __forceinline__ uint32_t smem_u32(const void* p) {
    uint32_t a;
    asm("{ .reg .u64 t; cvta.to.shared.u64 t, %1; cvt.u32.u64 %0, t; }"
        : "=r"(a) : "l"(p));
    return a;
}

__device__ __forceinline__ void split2(float x0, float x1, uint32_t& hi, uint32_t& lo) {
    uint32_t h;
    asm("cvt.rn.bf16x2.f32 %0, %1, %2;" : "=r"(h) : "f"(x1), "f"(x0));
    float h0 = __uint_as_float(h << 16);
    float h1 = __uint_as_float(h & 0xFFFF0000u);
    float r0 = x0 - h0;
    float r1 = x1 - h1;
    asm("cvt.rn.bf16x2.f32 %0, %1, %2;" : "=r"(lo) : "f"(r1), "f"(r0));
    hi = h;
}

#define LDMX4(r, addr)                                                        \
    asm volatile("ldmatrix.sync.aligned.m8n8.x4.shared.b16 {%0,%1,%2,%3}, [%4];" \
        : "=r"((r)[0]), "=r"((r)[1]), "=r"((r)[2]), "=r"((r)[3]) : "r"(addr))

#define LDMX4T(r, addr)                                                       \
    asm volatile("ldmatrix.sync.aligned.m8n8.x4.trans.shared.b16 {%0,%1,%2,%3}, [%4];" \
        : "=r"((r)[0]), "=r"((r)[1]), "=r"((r)[2]), "=r"((r)[3]) : "r"(addr))

#define MMA_BF16(acc, a, b0, b1)                                              \
    asm volatile("mma.sync.aligned.m16n8k16.row.col.f32.bf16.bf16.f32 "       \
        "{%0,%1,%2,%3}, {%4,%5,%6,%7}, {%8,%9}, {%0,%1,%2,%3};"               \
        : "+f"((acc)[0]), "+f"((acc)[1]), "+f"((acc)[2]), "+f"((acc)[3])      \
        : "r"((a)[0]), "r"((a)[1]), "r"((a)[2]), "r"((a)[3]), "r"(b0), "r"(b1))

// ---------------------------------------------------------------------------
// Prep: Mn[j][i] = (adj[i][j]!=0)/max(deg_j,1); Wl padded to 128 (fp32).
// ---------------------------------------------------------------------------
__global__ void prep_kernel(const int* __restrict__ adj, const float* __restrict__ Wl) {
    const int j = blockIdx.x;
    const int i = threadIdx.x;
    __shared__ int sdeg[NPAD];
    int a = (i < NN && j < NN) ? (adj[i * NN + j] != 0) : 0;
    sdeg[i] = a;
    __syncthreads();
#pragma unroll
    for (int s = 64; s > 0; s >>= 1) {
        if (i < s) sdeg[i] += sdeg[i + s];
        __syncthreads();
    }
    const int deg = sdeg[0];
    const float inv = (j < NN) ? 1.0f / (float)(deg > 1 ? deg : 1) : 0.0f;
    g_Mn [j * NPAD + i] = a ? inv : 0.0f;
    g_Wlp[j * NPAD + i] = (i < NN && j < NN) ? Wl[j * NN + i] : 0.0f;
}

// ===========================================================================
// tgemm: R8-proven big GEMM. CTA tile 128 x BNT, 256 thr, 8 warps (4m x 2n),
// warp tile 32 x (BNT/2). Writes fp32 partials to C + slice*PS.
// ===========================================================================
template<int BNT>
__global__ __launch_bounds__(NTH, 1)
void tgemm(const float* __restrict__ A1, int lda1, int ka1,
           const float* __restrict__ B1, int ldb1,
           const float* __restrict__ A2, int lda2, int ka2,
           const float* __restrict__ B2, int ldb2,
           int SPLITS,
           float* __restrict__ C, int ldc, int Mreal)
{
    constexpr int NTW = BNT / 16;
    constexpr int PITCHB = BNT + 8;
    constexpr int NBG = NTW / 2;
    constexpr int FB = BNT / 16;
    constexpr uint32_t AH_OFF = 0;
    constexpr uint32_t AL_OFF = BM * PITCHA * 2;
    constexpr uint32_t BH_OFF = 2 * BM * PITCHA * 2;
    constexpr uint32_t BBYTES = (uint32_t)BKC * PITCHB * 2;
    constexpr uint32_t BL_OFF = BH_OFF + BBYTES;
    constexpr uint32_t STAGE  = BH_OFF + 2 * BBYTES;

    extern __shared__ __align__(16) char dsm[];
    const uint32_t sb = smem_u32(dsm);

    const int tid = threadIdx.x;
    const int wid = tid >> 5;
    const int lid = tid & 31;
    const int ms = wid & 3;
    const int ns = wid >> 2;
    const int n0 = blockIdx.x * BNT;
    const int slice = blockIdx.y;

    const int pair = slice / SPLITS;
    const int q    = slice % SPLITS;
    const float* A = pair ? A2 : A1;
    const float* B = pair ? B2 : B1;
    const int lda = pair ? lda2 : lda1;
    const int ldb = pair ? ldb2 : ldb1;
    const int kaeff = (pair ? ka2 : ka1) / SPLITS;
    const int kbase = q * kaeff;
    const int T = kaeff / BKC;

    const int alrow = tid >> 4;
    const int alc   = (tid & 15) * 4;
    const int bkq = tid >> 2;
    const int bnq = (tid & 3) * (BNT / 4);

    float acc[2][NTW][4];
#pragma unroll
    for (int a = 0; a < 2; ++a)
#pragma unroll
        for (int b = 0; b < NTW; ++b)
#pragma unroll
            for (int c = 0; c < 4; ++c) acc[a][b][c] = 0.0f;

    const uint32_t aoffH = AH_OFF +
        (((uint32_t)(ms * 32 + (lid & 15)) * PITCHA) + ((lid >> 4) & 1) * 8u) * 2u;
    const uint32_t boff = BH_OFF +
        (((uint32_t)(lid & 15) * PITCHB) + (uint32_t)(ns * (BNT / 2) + (lid >> 4) * 8)) * 2u;

    float4 fa[8];
    float4 fbr[FB];
    const float4 f4z = make_float4(0.f, 0.f, 0.f, 0.f);

#define LOADG(T_)                                                              \
    do {                                                                       \
        int k0_ = kbase + (T_) * BKC;                                          \
        _Pragma("unroll")                                                      \
        for (int p = 0; p < 8; ++p) {                                          \
            int m = p * 16 + alrow;                                            \
            fa[p] = (m < Mreal) ? *(const float4*)(A + (size_t)m * lda + k0_ + alc) : f4z; \
        }                                                                      \
        const float* p_ = B + (size_t)(k0_ + bkq) * ldb + n0 + bnq;            \
        _Pragma("unroll")                                                      \
        for (int j = 0; j < FB; ++j)                                           \
            fbr[j] = *(const float4*)(p_ + j * 4);                             \
    } while (0)

#define STORE_STAGE(bufsel)                                                    \
    do {                                                                       \
        char* st = dsm + (bufsel) * STAGE;                                     \
        _Pragma("unroll")                                                      \
        for (int p = 0; p < 8; ++p) {                                          \
            int row = p * 16 + alrow;                                          \
            uint32_t h0, l0, h1, l1;                                           \
            split2(fa[p].x, fa[p].y, h0, l0);                                  \
            split2(fa[p].z, fa[p].w, h1, l1);                                  \
            uint32_t off = ((uint32_t)row * PITCHA + (uint32_t)alc) * 2u;      \
            *(uint2*)(st + AH_OFF + off) = make_uint2(h0, h1);                 \
            *(uint2*)(st + AL_OFF + off) = make_uint2(l0, l1);                 \
        }                                                                      \
        {                                                                      \
            uint32_t o_ = ((uint32_t)bkq * PITCHB + (uint32_t)bnq) * 2u;       \
            _Pragma("unroll")                                                  \
            for (int j = 0; j < FB; j += 2) {                                  \
                uint4 hv, lv;                                                  \
                split2(fbr[j].x,     fbr[j].y,     hv.x, lv.x);                \
                split2(fbr[j].z,     fbr[j].w,     hv.y, lv.y);                \
                split2(fbr[j + 1].x, fbr[j + 1].y, hv.z, lv.z);                \
                split2(fbr[j + 1].z, fbr[j + 1].w, hv.w, lv.w);                \
                *(uint4*)(st + BH_OFF + o_ + j * 8) = hv;                      \
                *(uint4*)(st + BL_OFF + o_ + j * 8) = lv;                      \
            }                                                                  \
        }                                                                      \
    } while (0)

    LOADG(0);
    STORE_STAGE(0);
    if (T > 1) LOADG(1);
    __syncthreads();

    for (int t = 0; t < T; ++t) {
        const uint32_t base = sb + (uint32_t)(t & 1) * STAGE;
#pragma unroll
        for (int ks = 0; ks < 4; ++ks) {
            const uint32_t kA = (uint32_t)ks * 32u;
            const uint32_t kB = (uint32_t)ks * 16u * PITCHB * 2u;
            uint32_t ah[2][4], al[2][4], bh[NBG][4], bl[NBG][4];
            LDMX4(ah[0], base + aoffH + kA);
            LDMX4(ah[1], base + aoffH + 16u * PITCHA * 2u + kA);
            LDMX4(al[0], base + aoffH + (AL_OFF - AH_OFF) + kA);
            LDMX4(al[1], base + aoffH + (AL_OFF - AH_OFF) + 16u * PITCHA * 2u + kA);
#pragma unroll
            for (int gp = 0; gp < NBG; ++gp) {
                LDMX4T(bh[gp], base + boff + gp * 32u + kB);
                LDMX4T(bl[gp], base + boff + (BL_OFF - BH_OFF) + gp * 32u + kB);
            }
#pragma unroll
            for (int mt = 0; mt < 2; ++mt)
#pragma unroll
                for (int nt = 0; nt < NTW; ++nt) {
                    const int gp = nt >> 1, ix = (nt & 1) * 2;
                    MMA_BF16(acc[mt][nt], ah[mt], bh[gp][ix], bh[gp][ix + 1]);
                    MMA_BF16(acc[mt][nt], ah[mt], bl[gp][ix], bl[gp][ix + 1]);
                    MMA_BF16(acc[mt][nt], al[mt], bh[gp][ix], bh[gp][ix + 1]);
                }
        }
        if (t + 1 < T) STORE_STAGE((t + 1) & 1);
        if (t + 2 < T) LOADG(t + 2);
        __syncthreads();
    }
#undef LOADG
#undef STORE_STAGE

    const int g  = lid >> 2;
    const int tq = lid & 3;
    float* Pout = C + (size_t)slice * PS;
#pragma unroll
    for (int mt = 0; mt < 2; ++mt) {
#pragma unroll
        for (int nt = 0; nt < NTW; ++nt) {
            int col = n0 + ns * (BNT / 2) + nt * 8 + tq * 2;
#pragma unroll
            for (int half = 0; half < 2; ++half) {
                int m = ms * 32 + mt * 16 + g + half * 8;
                if (m >= Mreal) continue;
                *(float2*)&Pout[(size_t)m * ldc + col] =
                    make_float2(acc[mt][nt][half * 2 + 0], acc[mt][nt][half * 2 + 1]);
            }
        }
    }
}

// ===========================================================================
// tgemm32f: small fused GEMM. CTA tile 128x32, 256 thr, 8 warps (4m x 2n),
// warp tile 32x16 (validated fragment math). K = 128 (T=2).
//   B[k][n] = (brelu? relu : id)( sum_{s<4} P_s[k][n] + bcol[n] )
//   computed in the loader; optionally materialized to hout (rows < NN).
// Epilogue: C = A @ B (+ rowbias per m).
// ===========================================================================
#define BNT32 32
#define PITCHB32 (BNT32 + 8)
#define AH32 0u
#define AL32 ((uint32_t)BM * PITCHA * 2u)            // 18432
#define BH32 (2u * AL32)                             // 36864
#define BB32 ((uint32_t)BKC * PITCHB32 * 2u)         // 5120
#define BL32 (BH32 + BB32)
#define ST32 (BH32 + 2u * BB32)                      // 47104
#define DS32 (2u * ST32)                             // 94208

__global__ __launch_bounds__(NTH, 1)
void tgemm32f(const float* __restrict__ A1,          // 128 x 128, lda = NPAD
              const float* __restrict__ P,           // 4 partial slices
              const float* __restrict__ bcol,        // column bias for B
              int brelu,
              float* __restrict__ hout,              // optional: materialize B
              const float* __restrict__ rowbias,     // optional per-row bias
              float* __restrict__ C, int ldc, int Mreal)
{
    extern __shared__ __align__(16) char dsm[];
    const uint32_t sb = smem_u32(dsm);

    const int tid = threadIdx.x;
    const int wid = tid >> 5;
    const int lid = tid & 31;
    const int ms = wid & 3;
    const int ns = wid >> 2;
    const int n0 = blockIdx.x * BNT32;

    const int T = NPAD / BKC;   // 2

    const int alrow = tid >> 4;
    const int alc   = (tid & 15) * 4;
    const int bkq = tid >> 2;                 // 0..63
    const int bnq = (tid & 3) * 8;            // 0,8,16,24

    float acc[2][2][4];
#pragma unroll
    for (int a = 0; a < 2; ++a)
#pragma unroll
        for (int b = 0; b < 2; ++b)
#pragma unroll
            for (int c = 0; c < 4; ++c) acc[a][b][c] = 0.0f;

    const uint32_t aoffH = AH32 +
        (((uint32_t)(ms * 32 + (lid & 15)) * PITCHA) + ((lid >> 4) & 1) * 8u) * 2u;
    const uint32_t boff = BH32 +
        (((uint32_t)(lid & 15) * PITCHB32) + (uint32_t)(ns * 16 + (lid >> 4) * 8)) * 2u;

    float4 fa[8];
    float4 fbr[2];
    const float4 f4z = make_float4(0.f, 0.f, 0.f, 0.f);

#define LOADG(T_)                                                              \
    do {                                                                       \
        int k0_ = (T_) * BKC;                                                  \
        _Pragma("unroll")                                                      \
        for (int p = 0; p < 8; ++p) {                                          \
            int m = p * 16 + alrow;                                            \
            fa[p] = (m < Mreal) ? *(const float4*)(A1 + (size_t)m * NPAD + k0_ + alc) : f4z; \
        }                                                                      \
        int krow = k0_ + bkq;                                                  \
        const float* pp = P + (size_t)krow * CC + n0 + bnq;                    \
        _Pragma("unroll")                                                      \
        for (int j = 0; j < 2; ++j) {                                          \
            float4 p0 = *(const float4*)(pp + j * 4);                          \
            float4 p1 = *(const float4*)(pp + PS + j * 4);                     \
            float4 p2 = *(const float4*)(pp + 2 * PS + j * 4);                 \
            float4 p3 = *(const float4*)(pp + 3 * PS + j * 4);                 \
            float4 bv = *(const float4*)(bcol + n0 + bnq + j * 4);             \
            float4 v;                                                          \
            v.x = (p0.x + p1.x) + (p2.x + p3.x) + bv.x;                        \
            v.y = (p0.y + p1.y) + (p2.y + p3.y) + bv.y;                        \
            v.z = (p0.z + p1.z) + (p2.z + p3.z) + bv.z;                        \
            v.w = (p0.w + p1.w) + (p2.w + p3.w) + bv.w;                        \
            if (brelu) {                                                       \
                v.x = fmaxf(v.x, 0.f); v.y = fmaxf(v.y, 0.f);                  \
                v.z = fmaxf(v.z, 0.f); v.w = fmaxf(v.w, 0.f);                  \
            }                                                                  \
            fbr[j] = v;                                                        \
        }                                                                      \
        if (hout != nullptr && krow < NN) {                                    \
            float* ho = hout + (size_t)krow * CC + n0 + bnq;                   \
            *(float4*)(ho)     = fbr[0];                                       \
            *(float4*)(ho + 4) = fbr[1];                                       \
        }                                                                      \
    } while (0)

#define STORE_STAGE(bufsel)                                                    \
    do {                                                                       \
        char* st = dsm + (bufsel) * ST32;                                      \
        _Pragma("unroll")                                                      \
        for (int p = 0; p < 8; ++p) {                                          \
            int row = p * 16 + alrow;                                          \
            uint32_t h0, l0, h1, l1;                                           \
            split2(fa[p].x, fa[p].y, h0, l0);                                  \
            split2(fa[p].z, fa[p].w, h1, l1);                                  \
            uint32_t off = ((uint32_t)row * PITCHA + (uint32_t)alc) * 2u;      \
            *(uint2*)(st + AH32 + off) = make_uint2(h0, h1);                   \
            *(uint2*)(st + AL32 + off) = make_uint2(l0, l1);                   \
        }                                                                      \
        {                                                                      \
            uint32_t o_ = ((uint32_t)bkq * PITCHB32 + (uint32_t)bnq) * 2u;     \
            uint4 hv, lv;                                                      \
            split2(fbr[0].x, fbr[0].y, hv.x, lv.x);                            \
            split2(fbr[0].z, fbr[0].w, hv.y, lv.y);                            \
            split2(fbr[1].x, fbr[1].y, hv.z, lv.z);                            \
            split2(fbr[1].z, fbr[1].w, hv.w, lv.w);                            \
            *(uint4*)(st + BH32 + o_) = hv;                                    \
            *(uint4*)(st + BL32 + o_) = lv;                                    \
        }                                                                      \
    } while (0)

    LOADG(0);
    STORE_STAGE(0);
    LOADG(1);
    __syncthreads();

    for (int t = 0; t < T; ++t) {
        const uint32_t base = sb + (uint32_t)(t & 1) * ST32;
#pragma unroll
        for (int ks = 0; ks < 4; ++ks) {
            const uint32_t kA = (uint32_t)ks * 32u;
            const uint32_t kB = (uint32_t)ks * 16u * PITCHB32 * 2u;
            uint32_t ah[2][4], al[2][4], bh[4], bl[4];
            LDMX4(ah[0], base + aoffH + kA);
            LDMX4(ah[1], base + aoffH + 16u * PITCHA * 2u + kA);
            LDMX4(al[0], base + aoffH + (AL32 - AH32) + kA);
            LDMX4(al[1], base + aoffH + (AL32 - AH32) + 16u * PITCHA * 2u + kA);
            LDMX4T(bh, base + boff + kB);
            LDMX4T(bl, base + boff + (BL32 - BH32) + kB);
#pragma unroll
            for (int mt = 0; mt < 2; ++mt)
#pragma unroll
                for (int nt = 0; nt < 2; ++nt) {
                    const int ix = nt * 2;
                    MMA_BF16(acc[mt][nt], ah[mt], bh[ix], bh[ix + 1]);
                    MMA_BF16(acc[mt][nt], ah[mt], bl[ix], bl[ix + 1]);
                    MMA_BF16(acc[mt][nt], al[mt], bh[ix], bh[ix + 1]);
                }
        }
        if (t + 1 < T) STORE_STAGE((t + 1) & 1);
        __syncthreads();
    }
#undef LOADG
#undef STORE_STAGE

    const int g  = lid >> 2;
    const int tq = lid & 3;
#pragma unroll
    for (int mt = 0; mt < 2; ++mt) {
#pragma unroll
        for (int nt = 0; nt < 2; ++nt) {
            int col = n0 + ns * 16 + nt * 8 + tq * 2;
#pragma unroll
            for (int half = 0; half < 2; ++half) {
                int m = ms * 32 + mt * 16 + g + half * 8;
                if (m >= Mreal) continue;
                float rb = (rowbias != nullptr) ? rowbias[m] : 0.0f;
                float vx = acc[mt][nt][half * 2 + 0] + rb;
                float vy = acc[mt][nt][half * 2 + 1] + rb;
                *(float2*)&C[(size_t)m * ldc + col] = make_float2(vx, vy);
            }
        }
    }
}

// ---------------------------------------------------------------------------
extern "C" void kernel_launch(void* const* d_in, const int* in_sizes, int n_in,
                              void* d_out, int out_size)
{
    const float* x   = (const float*)d_in[0];
    const int*   adj = (const int*)  d_in[1];
    const float* W2  = (const float*)d_in[2];
    const float* b2  = (const float*)d_in[3];
    const float* W1  = (const float*)d_in[4];
    const float* b1  = (const float*)d_in[5];
    const float* Wl  = (const float*)d_in[6];
    const float* bl  = (const float*)d_in[7];
    float* out = (float*)d_out;

    float *h, *aggr, *Mn, *Wlp, *P;
    cudaGetSymbolAddress((void**)&h,    g_h);
    cudaGetSymbolAddress((void**)&aggr, g_aggr);
    cudaGetSymbolAddress((void**)&Mn,   g_Mn);
    cudaGetSymbolAddress((void**)&Wlp,  g_Wlp);
    cudaGetSymbolAddress((void**)&P,    g_P);

    const int DS128 = 2 * (2 * BM * PITCHA * 2 + 2 * BKC * (128 + 8) * 2);   // 143360
    cudaFuncSetAttribute(tgemm<128>, cudaFuncAttributeMaxDynamicSharedMemorySize, DS128);
    cudaFuncSetAttribute(tgemm32f, cudaFuncAttributeMaxDynamicSharedMemorySize, DS32);

    dim3 b(NTH);
    dim3 gBig(CC / 128, 4);    // 32 x 4 slices = 128 CTAs
    dim3 gF  (CC / BNT32);     // 128 CTAs

    prep_kernel<<<NPAD, NPAD>>>(adj, Wl);

    // K1: P_s = x @ W2 over 4 k-slices of 1024
    tgemm<128><<<gBig, b, DS128>>>(x, CC, CC, W2, CC,
                                   nullptr, 0, 0, nullptr, 0,
                                   /*SPLITS=*/4, P, CC, NN);

    // K2 (fused): B = h = sum P + b2 (materialized to g_h); aggr = Mn @ h
    tgemm32f<<<gF, b, DS32>>>(Mn, P, b2, /*brelu=*/0,
                              /*hout=*/h, /*rowbias=*/nullptr,
                              aggr, CC, NN);

    // K3: P_s = (h @ W1_top | aggr @ W1_bot), each pair split in 2
    tgemm<128><<<gBig, b, DS128>>>(h, CC, CC, W1, CC,
                                   aggr, CC, CC, W1 + (size_t)CC * CC, CC,
                                   /*SPLITS=*/2, P, CC, NN);

    // K4 (fused): B = out1 = relu(sum P + b1) (never materialized);
    //             out = Wlp @ out1 + bl[:,None]
    tgemm32f<<<gF, b, DS32>>>(Wlp, P, b1, /*brelu=*/1,
                              /*hout=*/nullptr, /*rowbias=*/bl,
                              out, CC, NN);
}

// round 13
// speedup vs baseline: 1.5001x; 1.2130x over previous
#include <cuda_runtime.h>
#include <cuda_bf16.h>
#include <cuda_fp16.h>
#include <cstdint>

#define NN 110
#define CC 4096
#define NPAD 128

#define BM 128
#define BKC 64          // fp32 k per chunk
#define PITCHA 72       // 16-bit elems per A smem row (64 + 8 pad)
#define NTH 256

#define PS (NPAD * CC)  // partial buffer stride

// -------------------- scratch (zero-initialized device globals) ------------
__device__ float g_h   [NPAD * CC];
__device__ float g_aggr[NPAD * CC];
__device__ float g_Mn  [NPAD * NPAD];
__device__ float g_Wlp [NPAD * NPAD];
__device__ float g_P   [4 * PS];

// -------------------- helpers ----------------------------------------------
__device__ __forceinline__ uint32_t smem_u32(const void* p) {
    uint32_t a;
    asm("{ .reg .u64 t; cvta.to.shared.u64 t, %1; cvt.u32.u64 %0, t; }"
        : "=r"(a) : "l"(p));
    return a;
}

// bf16 split (kept for the small fused kernels)
__device__ __forceinline__ void split2(float x0, float x1, uint32_t& hi, uint32_t& lo) {
    uint32_t h;
    asm("cvt.rn.bf16x2.f32 %0, %1, %2;" : "=r"(h) : "f"(x1), "f"(x0));
    float h0 = __uint_as_float(h << 16);
    float h1 = __uint_as_float(h & 0xFFFF0000u);
    float r0 = x0 - h0;
    float r1 = x1 - h1;
    asm("cvt.rn.bf16x2.f32 %0, %1, %2;" : "=r"(lo) : "f"(r1), "f"(r0));
    hi = h;
}

// fp16 split: hi = f16x2(x), lo = f16x2(x - float(hi))
__device__ __forceinline__ void splith2(float x0, float x1, uint32_t& hi, uint32_t& lo) {
    uint32_t h;
    asm("cvt.rn.f16x2.f32 %0, %1, %2;" : "=r"(h) : "f"(x1), "f"(x0));
    float h0, h1;
    asm("{ .reg .f16 a, b;\n"
        " mov.b32 {a, b}, %2;\n"
        " cvt.f32.f16 %0, a;\n"
        " cvt.f32.f16 %1, b; }"
        : "=f"(h0), "=f"(h1) : "r"(h));
    float r0 = x0 - h0;
    float r1 = x1 - h1;
    asm("cvt.rn.f16x2.f32 %0, %1, %2;" : "=r"(lo) : "f"(r1), "f"(r0));
    hi = h;
}

__device__ __forceinline__ uint32_t cvth2(float x0, float x1) {
    uint32_t h;
    asm("cvt.rn.f16x2.f32 %0, %1, %2;" : "=r"(h) : "f"(x1), "f"(x0));
    return h;
}

#define LDMX4(r, addr)                                                        \
    asm volatile("ldmatrix.sync.aligned.m8n8.x4.shared.b16 {%0,%1,%2,%3}, [%4];" \
        : "=r"((r)[0]), "=r"((r)[1]), "=r"((r)[2]), "=r"((r)[3]) : "r"(addr))

#define LDMX4T(r, addr)                                                       \
    asm volatile("ldmatrix.sync.aligned.m8n8.x4.trans.shared.b16 {%0,%1,%2,%3}, [%4];" \
        : "=r"((r)[0]), "=r"((r)[1]), "=r"((r)[2]), "=r"((r)[3]) : "r"(addr))

#define MMA_BF16(acc, a, b0, b1)                                              \
    asm volatile("mma.sync.aligned.m16n8k16.row.col.f32.bf16.bf16.f32 "       \
        "{%0,%1,%2,%3}, {%4,%5,%6,%7}, {%8,%9}, {%0,%1,%2,%3};"               \
        : "+f"((acc)[0]), "+f"((acc)[1]), "+f"((acc)[2]), "+f"((acc)[3])      \
        : "r"((a)[0]), "r"((a)[1]), "r"((a)[2]), "r"((a)[3]), "r"(b0), "r"(b1))

#define MMA_F16(acc, a, b0, b1)                                               \
    asm volatile("mma.sync.aligned.m16n8k16.row.col.f32.f16.f16.f32 "         \
        "{%0,%1,%2,%3}, {%4,%5,%6,%7}, {%8,%9}, {%0,%1,%2,%3};"               \
        : "+f"((acc)[0]), "+f"((acc)[1]), "+f"((acc)[2]), "+f"((acc)[3])      \
        : "r"((a)[0]), "r"((a)[1]), "r"((a)[2]), "r"((a)[3]), "r"(b0), "r"(b1))

// ---------------------------------------------------------------------------
// Prep: Mn[j][i] = (adj[i][j]!=0)/max(deg_j,1); Wl padded to 128 (fp32).
// ---------------------------------------------------------------------------
__global__ void prep_kernel(const int* __restrict__ adj, const float* __restrict__ Wl) {
    const int j = blockIdx.x;
    const int i = threadIdx.x;
    __shared__ int sdeg[NPAD];
    int a = (i < NN && j < NN) ? (adj[i * NN + j] != 0) : 0;
    sdeg[i] = a;
    __syncthreads();
#pragma unroll
    for (int s = 64; s > 0; s >>= 1) {
        if (i < s) sdeg[i] += sdeg[i + s];
        __syncthreads();
    }
    const int deg = sdeg[0];
    const float inv = (j < NN) ? 1.0f / (float)(deg > 1 ? deg : 1) : 0.0f;
    g_Mn [j * NPAD + i] = a ? inv : 0.0f;
    g_Wlp[j * NPAD + i] = (i < NN && j < NN) ? Wl[j * NN + i] : 0.0f;
}

// ===========================================================================
// tgemm: big GEMM, fp16 2-term split (A = Ah + Al, B = Bh only).
// CTA tile 128 x BNT, 256 thr, 8 warps (4m x 2n), warp tile 32 x (BNT/2).
// Writes fp32 partials to C + slice*PS.
// ===========================================================================
template<int BNT>
__global__ __launch_bounds__(NTH, 1)
void tgemm(const float* __restrict__ A1, int lda1, int ka1,
           const float* __restrict__ B1, int ldb1,
           const float* __restrict__ A2, int lda2, int ka2,
           const float* __restrict__ B2, int ldb2,
           int SPLITS,
           float* __restrict__ C, int ldc, int Mreal)
{
    constexpr int NTW = BNT / 16;
    constexpr int PITCHB = BNT + 8;
    constexpr int NBG = NTW / 2;
    constexpr int FB = BNT / 16;
    constexpr uint32_t AH_OFF = 0;
    constexpr uint32_t AL_OFF = BM * PITCHA * 2;             // 18432
    constexpr uint32_t BH_OFF = 2 * BM * PITCHA * 2;         // 36864
    constexpr uint32_t BBYTES = (uint32_t)BKC * PITCHB * 2;  // 17408 @BNT=128
    constexpr uint32_t STAGE  = BH_OFF + BBYTES;             // 54272

    extern __shared__ __align__(16) char dsm[];
    const uint32_t sb = smem_u32(dsm);

    const int tid = threadIdx.x;
    const int wid = tid >> 5;
    const int lid = tid & 31;
    const int ms = wid & 3;
    const int ns = wid >> 2;
    const int n0 = blockIdx.x * BNT;
    const int slice = blockIdx.y;

    const int pair = slice / SPLITS;
    const int q    = slice % SPLITS;
    const float* A = pair ? A2 : A1;
    const float* B = pair ? B2 : B1;
    const int lda = pair ? lda2 : lda1;
    const int ldb = pair ? ldb2 : ldb1;
    const int kaeff = (pair ? ka2 : ka1) / SPLITS;
    const int kbase = q * kaeff;
    const int T = kaeff / BKC;

    const int alrow = tid >> 4;
    const int alc   = (tid & 15) * 4;
    const int bkq = tid >> 2;
    const int bnq = (tid & 3) * (BNT / 4);

    float acc[2][NTW][4];
#pragma unroll
    for (int a = 0; a < 2; ++a)
#pragma unroll
        for (int b = 0; b < NTW; ++b)
#pragma unroll
            for (int c = 0; c < 4; ++c) acc[a][b][c] = 0.0f;

    const uint32_t aoffH = AH_OFF +
        (((uint32_t)(ms * 32 + (lid & 15)) * PITCHA) + ((lid >> 4) & 1) * 8u) * 2u;
    const uint32_t boff = BH_OFF +
        (((uint32_t)(lid & 15) * PITCHB) + (uint32_t)(ns * (BNT / 2) + (lid >> 4) * 8)) * 2u;

    float4 fa[8];
    float4 fbr[FB];
    const float4 f4z = make_float4(0.f, 0.f, 0.f, 0.f);

#define LOADG(T_)                                                              \
    do {                                                                       \
        int k0_ = kbase + (T_) * BKC;                                          \
        _Pragma("unroll")                                                      \
        for (int p = 0; p < 8; ++p) {                                          \
            int m = p * 16 + alrow;                                            \
            fa[p] = (m < Mreal) ? *(const float4*)(A + (size_t)m * lda + k0_ + alc) : f4z; \
        }                                                                      \
        const float* p_ = B + (size_t)(k0_ + bkq) * ldb + n0 + bnq;            \
        _Pragma("unroll")                                                      \
        for (int j = 0; j < FB; ++j)                                           \
            fbr[j] = *(const float4*)(p_ + j * 4);                             \
    } while (0)

#define STORE_STAGE(bufsel)                                                    \
    do {                                                                       \
        char* st = dsm + (bufsel) * STAGE;                                     \
        _Pragma("unroll")                                                      \
        for (int p = 0; p < 8; ++p) {                                          \
            int row = p * 16 + alrow;                                          \
            uint32_t h0, l0, h1, l1;                                           \
            splith2(fa[p].x, fa[p].y, h0, l0);                                 \
            splith2(fa[p].z, fa[p].w, h1, l1);                                 \
            uint32_t off = ((uint32_t)row * PITCHA + (uint32_t)alc) * 2u;      \
            *(uint2*)(st + AH_OFF + off) = make_uint2(h0, h1);                 \
            *(uint2*)(st + AL_OFF + off) = make_uint2(l0, l1);                 \
        }                                                                      \
        {                                                                      \
            uint32_t o_ = ((uint32_t)bkq * PITCHB + (uint32_t)bnq) * 2u;       \
            _Pragma("unroll")                                                  \
            for (int j = 0; j < FB; j += 2) {                                  \
                uint4 hv;                                                      \
                hv.x = cvth2(fbr[j].x,     fbr[j].y);                          \
                hv.y = cvth2(fbr[j].z,     fbr[j].w);                          \
                hv.z = cvth2(fbr[j + 1].x, fbr[j + 1].y);                      \
                hv.w = cvth2(fbr[j + 1].z, fbr[j + 1].w);                      \
                *(uint4*)(st + BH_OFF + o_ + j * 8) = hv;                      \
            }                                                                  \
        }                                                                      \
    } while (0)

    LOADG(0);
    STORE_STAGE(0);
    if (T > 1) LOADG(1);
    __syncthreads();

    for (int t = 0; t < T; ++t) {
        const uint32_t base = sb + (uint32_t)(t & 1) * STAGE;
#pragma unroll
        for (int ks = 0; ks < 4; ++ks) {
            const uint32_t kA = (uint32_t)ks * 32u;
            const uint32_t kB = (uint32_t)ks * 16u * PITCHB * 2u;
            uint32_t ah[2][4], al[2][4], bh[NBG][4];
            LDMX4(ah[0], base + aoffH + kA);
            LDMX4(ah[1], base + aoffH + 16u * PITCHA * 2u + kA);
            LDMX4(al[0], base + aoffH + (AL_OFF - AH_OFF) + kA);
            LDMX4(al[1], base + aoffH + (AL_OFF - AH_OFF) + 16u * PITCHA * 2u + kA);
#pragma unroll
            for (int gp = 0; gp < NBG; ++gp)
                LDMX4T(bh[gp], base + boff + gp * 32u + kB);
#pragma unroll
            for (int mt = 0; mt < 2; ++mt)
#pragma unroll
                for (int nt = 0; nt < NTW; ++nt) {
                    const int gp = nt >> 1, ix = (nt & 1) * 2;
                    MMA_F16(acc[mt][nt], ah[mt], bh[gp][ix], bh[gp][ix + 1]);
                    MMA_F16(acc[mt][nt], al[mt], bh[gp][ix], bh[gp][ix + 1]);
                }
        }
        if (t + 1 < T) STORE_STAGE((t + 1) & 1);
        if (t + 2 < T) LOADG(t + 2);
        __syncthreads();
    }
#undef LOADG
#undef STORE_STAGE

    const int g  = lid >> 2;
    const int tq = lid & 3;
    float* Pout = C + (size_t)slice * PS;
#pragma unroll
    for (int mt = 0; mt < 2; ++mt) {
#pragma unroll
        for (int nt = 0; nt < NTW; ++nt) {
            int col = n0 + ns * (BNT / 2) + nt * 8 + tq * 2;
#pragma unroll
            for (int half = 0; half < 2; ++half) {
                int m = ms * 32 + mt * 16 + g + half * 8;
                if (m >= Mreal) continue;
                *(float2*)&Pout[(size_t)m * ldc + col] =
                    make_float2(acc[mt][nt][half * 2 + 0], acc[mt][nt][half * 2 + 1]);
            }
        }
    }
}

// ===========================================================================
// tgemm32f: small fused GEMM (bf16 3-term, R12-proven). CTA tile 128x32,
// 256 thr, 8 warps (4m x 2n), warp tile 32x16. K = 128 (T=2).
//   B[k][n] = (brelu? relu : id)( sum_{s<4} P_s[k][n] + bcol[n] )
//   computed in the loader; optionally materialized to hout (rows < NN).
// Epilogue: C = A @ B (+ rowbias per m).
// ===========================================================================
#define BNT32 32
#define PITCHB32 (BNT32 + 8)
#define AH32 0u
#define AL32 ((uint32_t)BM * PITCHA * 2u)            // 18432
#define BH32 (2u * AL32)                             // 36864
#define BB32 ((uint32_t)BKC * PITCHB32 * 2u)         // 5120
#define BL32 (BH32 + BB32)
#define ST32 (BH32 + 2u * BB32)                      // 47104
#define DS32 (2u * ST32)                             // 94208

__global__ __launch_bounds__(NTH, 1)
void tgemm32f(const float* __restrict__ A1,          // 128 x 128, lda = NPAD
              const float* __restrict__ P,           // 4 partial slices
              const float* __restrict__ bcol,        // column bias for B
              int brelu,
              float* __restrict__ hout,              // optional: materialize B
              const float* __restrict__ rowbias,     // optional per-row bias
              float* __restrict__ C, int ldc, int Mreal)
{
    extern __shared__ __align__(16) char dsm[];
    const uint32_t sb = smem_u32(dsm);

    const int tid = threadIdx.x;
    const int wid = tid >> 5;
    const int lid = tid & 31;
    const int ms = wid & 3;
    const int ns = wid >> 2;
    const int n0 = blockIdx.x * BNT32;

    const int T = NPAD / BKC;   // 2

    const int alrow = tid >> 4;
    const int alc   = (tid & 15) * 4;
    const int bkq = tid >> 2;                 // 0..63
    const int bnq = (tid & 3) * 8;            // 0,8,16,24

    float acc[2][2][4];
#pragma unroll
    for (int a = 0; a < 2; ++a)
#pragma unroll
        for (int b = 0; b < 2; ++b)
#pragma unroll
            for (int c = 0; c < 4; ++c) acc[a][b][c] = 0.0f;

    const uint32_t aoffH = AH32 +
        (((uint32_t)(ms * 32 + (lid & 15)) * PITCHA) + ((lid >> 4) & 1) * 8u) * 2u;
    const uint32_t boff = BH32 +
        (((uint32_t)(lid & 15) * PITCHB32) + (uint32_t)(ns * 16 + (lid >> 4) * 8)) * 2u;

    float4 fa[8];
    float4 fbr[2];
    const float4 f4z = make_float4(0.f, 0.f, 0.f, 0.f);

#define LOADG(T_)                                                              \
    do {                                                                       \
        int k0_ = (T_) * BKC;                                                  \
        _Pragma("unroll")                                                      \
        for (int p = 0; p < 8; ++p) {                                          \
            int m = p * 16 + alrow;                                            \
            fa[p] = (m < Mreal) ? *(const float4*)(A1 + (size_t)m * NPAD + k0_ + alc) : f4z; \
        }                                                                      \
        int krow = k0_ + bkq;                                                  \
        const float* pp = P + (size_t)krow * CC + n0 + bnq;                    \
        _Pragma("unroll")                                                      \
        for (int j = 0; j < 2; ++j) {                                          \
            float4 p0 = *(const float4*)(pp + j * 4);                          \
            float4 p1 = *(const float4*)(pp + PS + j * 4);                     \
            float4 p2 = *(const float4*)(pp + 2 * PS + j * 4);                 \
            float4 p3 = *(const float4*)(pp + 3 * PS + j * 4);                 \
            float4 bv = *(const float4*)(bcol + n0 + bnq + j * 4);             \
            float4 v;                                                          \
            v.x = (p0.x + p1.x) + (p2.x + p3.x) + bv.x;                        \
            v.y = (p0.y + p1.y) + (p2.y + p3.y) + bv.y;                        \
            v.z = (p0.z + p1.z) + (p2.z + p3.z) + bv.z;                        \
            v.w = (p0.w + p1.w) + (p2.w + p3.w) + bv.w;                        \
            if (brelu) {                                                       \
                v.x = fmaxf(v.x, 0.f); v.y = fmaxf(v.y, 0.f);                  \
                v.z = fmaxf(v.z, 0.f); v.w = fmaxf(v.w, 0.f);                  \
            }                                                                  \
            fbr[j] = v;                                                        \
        }                                                                      \
        if (hout != nullptr && krow < NN) {                                    \
            float* ho = hout + (size_t)krow * CC + n0 + bnq;                   \
            *(float4*)(ho)     = fbr[0];                                       \
            *(float4*)(ho + 4) = fbr[1];                                       \
        }                                                                      \
    } while (0)

#define STORE_STAGE(bufsel)                                                    \
    do {                                                                       \
        char* st = dsm + (bufsel) * ST32;                                      \
        _Pragma("unroll")                                                      \
        for (int p = 0; p < 8; ++p) {                                          \
            int row = p * 16 + alrow;                                          \
            uint32_t h0, l0, h1, l1;                                           \
            split2(fa[p].x, fa[p].y, h0, l0);                                  \
            split2(fa[p].z, fa[p].w, h1, l1);                                  \
            uint32_t off = ((uint32_t)row * PITCHA + (uint32_t)alc) * 2u;      \
            *(uint2*)(st + AH32 + off) = make_uint2(h0, h1);                   \
            *(uint2*)(st + AL32 + off) = make_uint2(l0, l1);                   \
        }                                                                      \
        {                                                                      \
            uint32_t o_ = ((uint32_t)bkq * PITCHB32 + (uint32_t)bnq) * 2u;     \
            uint4 hv, lv;                                                      \
            split2(fbr[0].x, fbr[0].y, hv.x, lv.x);                            \
            split2(fbr[0].z, fbr[0].w, hv.y, lv.y);                            \
            split2(fbr[1].x, fbr[1].y, hv.z, lv.z);                            \
            split2(fbr[1].z, fbr[1].w, hv.w, lv.w);                            \
            *(uint4*)(st + BH32 + o_) = hv;                                    \
            *(uint4*)(st + BL32 + o_) = lv;                                    \
        }                                                                      \
    } while (0)

    LOADG(0);
    STORE_STAGE(0);
    LOADG(1);
    __syncthreads();

    for (int t = 0; t < T; ++t) {
        const uint32_t base = sb + (uint32_t)(t & 1) * ST32;
#pragma unroll
        for (int ks = 0; ks < 4; ++ks) {
            const uint32_t kA = (uint32_t)ks * 32u;
            const uint32_t kB = (uint32_t)ks * 16u * PITCHB32 * 2u;
            uint32_t ah[2][4], al[2][4], bh[4], bl[4];
            LDMX4(ah[0], base + aoffH + kA);
            LDMX4(ah[1], base + aoffH + 16u * PITCHA * 2u + kA);
            LDMX4(al[0], base + aoffH + (AL32 - AH32) + kA);
            LDMX4(al[1], base + aoffH + (AL32 - AH32) + 16u * PITCHA * 2u + kA);
            LDMX4T(bh, base + boff + kB);
            LDMX4T(bl, base + boff + (BL32 - BH32) + kB);
#pragma unroll
            for (int mt = 0; mt < 2; ++mt)
#pragma unroll
                for (int nt = 0; nt < 2; ++nt) {
                    const int ix = nt * 2;
                    MMA_BF16(acc[mt][nt], ah[mt], bh[ix], bh[ix + 1]);
                    MMA_BF16(acc[mt][nt], ah[mt], bl[ix], bl[ix + 1]);
                    MMA_BF16(acc[mt][nt], al[mt], bh[ix], bh[ix + 1]);
                }
        }
        if (t + 1 < T) STORE_STAGE((t + 1) & 1);
        __syncthreads();
    }
#undef LOADG
#undef STORE_STAGE

    const int g  = lid >> 2;
    const int tq = lid & 3;
#pragma unroll
    for (int mt = 0; mt < 2; ++mt) {
#pragma unroll
        for (int nt = 0; nt < 2; ++nt) {
            int col = n0 + ns * 16 + nt * 8 + tq * 2;
#pragma unroll
            for (int half = 0; half < 2; ++half) {
                int m = ms * 32 + mt * 16 + g + half * 8;
                if (m >= Mreal) continue;
                float rb = (rowbias != nullptr) ? rowbias[m] : 0.0f;
                float vx = acc[mt][nt][half * 2 + 0] + rb;
                float vy = acc[mt][nt][half * 2 + 1] + rb;
                *(float2*)&C[(size_t)m * ldc + col] = make_float2(vx, vy);
            }
        }
    }
}

// ---------------------------------------------------------------------------
extern "C" void kernel_launch(void* const* d_in, const int* in_sizes, int n_in,
                              void* d_out, int out_size)
{
    const float* x   = (const float*)d_in[0];
    const int*   adj = (const int*)  d_in[1];
    const float* W2  = (const float*)d_in[2];
    const float* b2  = (const float*)d_in[3];
    const float* W1  = (const float*)d_in[4];
    const float* b1  = (const float*)d_in[5];
    const float* Wl  = (const float*)d_in[6];
    const float* bl  = (const float*)d_in[7];
    float* out = (float*)d_out;

    float *h, *aggr, *Mn, *Wlp, *P;
    cudaGetSymbolAddress((void**)&h,    g_h);
    cudaGetSymbolAddress((void**)&aggr, g_aggr);
    cudaGetSymbolAddress((void**)&Mn,   g_Mn);
    cudaGetSymbolAddress((void**)&Wlp,  g_Wlp);
    cudaGetSymbolAddress((void**)&P,    g_P);

    // fp16 2-term stage: AH + AL + BH only
    const int DS128 = 2 * (2 * BM * PITCHA * 2 + BKC * (128 + 8) * 2);   // 108544
    cudaFuncSetAttribute(tgemm<128>, cudaFuncAttributeMaxDynamicSharedMemorySize, DS128);
    cudaFuncSetAttribute(tgemm32f, cudaFuncAttributeMaxDynamicSharedMemorySize, DS32);

    dim3 b(NTH);
    dim3 gBig(CC / 128, 4);    // 32 x 4 slices = 128 CTAs
    dim3 gF  (CC / BNT32);     // 128 CTAs

    prep_kernel<<<NPAD, NPAD>>>(adj, Wl);

    // K1: P_s = x @ W2 over 4 k-slices of 1024 (fp16 2-term)
    tgemm<128><<<gBig, b, DS128>>>(x, CC, CC, W2, CC,
                                   nullptr, 0, 0, nullptr, 0,
                                   /*SPLITS=*/4, P, CC, NN);

    // K2 (fused): B = h = sum P + b2 (materialized to g_h); aggr = Mn @ h
    tgemm32f<<<gF, b, DS32>>>(Mn, P, b2, /*brelu=*/0,
                              /*hout=*/h, /*rowbias=*/nullptr,
                              aggr, CC, NN);

    // K3: P_s = (h @ W1_top | aggr @ W1_bot), each pair split in 2 (fp16 2-term)
    tgemm<128><<<gBig, b, DS128>>>(h, CC, CC, W1, CC,
                                   aggr, CC, CC, W1 + (size_t)CC * CC, CC,
                                   /*SPLITS=*/2, P, CC, NN);

    // K4 (fused): B = out1 = relu(sum P + b1) (never materialized);
    //             out = Wlp @ out1 + bl[:,None]
    tgemm32f<<<gF, b, DS32>>>(Wlp, P, b1, /*brelu=*/1,
                              /*hout=*/nullptr, /*rowbias=*/bl,
                              out, CC, NN);
}

// round 14
// speedup vs baseline: 1.6719x; 1.1145x over previous
#include <cuda_runtime.h>
#include <cuda_bf16.h>
#include <cuda_fp16.h>
#include <cstdint>

#define NN 110
#define CC 4096
#define NPAD 128

#define BM 128
#define BKC 64          // fp32 k per chunk
#define PITCHA 72       // 16-bit elems per A smem row (64 + 8 pad)
#define NTH 256

#define PS (NPAD * CC)  // partial buffer stride

// -------------------- scratch (zero-initialized device globals) ------------
__device__ float g_h   [NPAD * CC];
__device__ float g_aggr[NPAD * CC];
__device__ float g_Mn  [NPAD * NPAD];
__device__ float g_Wlp [NPAD * NPAD];
__device__ float g_P   [4 * PS];

// -------------------- helpers ----------------------------------------------
__device__ __forceinline__ uint32_t smem_u32(const void* p) {
    uint32_t a;
    asm("{ .reg .u64 t; cvta.to.shared.u64 t, %1; cvt.u32.u64 %0, t; }"
        : "=r"(a) : "l"(p));
    return a;
}

// bf16 split (kept for the small fused kernels)
__device__ __forceinline__ void split2(float x0, float x1, uint32_t& hi, uint32_t& lo) {
    uint32_t h;
    asm("cvt.rn.bf16x2.f32 %0, %1, %2;" : "=r"(h) : "f"(x1), "f"(x0));
    float h0 = __uint_as_float(h << 16);
    float h1 = __uint_as_float(h & 0xFFFF0000u);
    float r0 = x0 - h0;
    float r1 = x1 - h1;
    asm("cvt.rn.bf16x2.f32 %0, %1, %2;" : "=r"(lo) : "f"(r1), "f"(r0));
    hi = h;
}

__device__ __forceinline__ uint32_t cvth2(float x0, float x1) {
    uint32_t h;
    asm("cvt.rn.f16x2.f32 %0, %1, %2;" : "=r"(h) : "f"(x1), "f"(x0));
    return h;
}

#define LDMX4(r, addr)                                                        \
    asm volatile("ldmatrix.sync.aligned.m8n8.x4.shared.b16 {%0,%1,%2,%3}, [%4];" \
        : "=r"((r)[0]), "=r"((r)[1]), "=r"((r)[2]), "=r"((r)[3]) : "r"(addr))

#define LDMX4T(r, addr)                                                       \
    asm volatile("ldmatrix.sync.aligned.m8n8.x4.trans.shared.b16 {%0,%1,%2,%3}, [%4];" \
        : "=r"((r)[0]), "=r"((r)[1]), "=r"((r)[2]), "=r"((r)[3]) : "r"(addr))

#define MMA_BF16(acc, a, b0, b1)                                              \
    asm volatile("mma.sync.aligned.m16n8k16.row.col.f32.bf16.bf16.f32 "       \
        "{%0,%1,%2,%3}, {%4,%5,%6,%7}, {%8,%9}, {%0,%1,%2,%3};"               \
        : "+f"((acc)[0]), "+f"((acc)[1]), "+f"((acc)[2]), "+f"((acc)[3])      \
        : "r"((a)[0]), "r"((a)[1]), "r"((a)[2]), "r"((a)[3]), "r"(b0), "r"(b1))

#define MMA_F16(acc, a, b0, b1)                                               \
    asm volatile("mma.sync.aligned.m16n8k16.row.col.f32.f16.f16.f32 "         \
        "{%0,%1,%2,%3}, {%4,%5,%6,%7}, {%8,%9}, {%0,%1,%2,%3};"               \
        : "+f"((acc)[0]), "+f"((acc)[1]), "+f"((acc)[2]), "+f"((acc)[3])      \
        : "r"((a)[0]), "r"((a)[1]), "r"((a)[2]), "r"((a)[3]), "r"(b0), "r"(b1))

// ---------------------------------------------------------------------------
// Prep: Mn[j][i] = (adj[i][j]!=0)/max(deg_j,1); Wl padded to 128 (fp32).
// ---------------------------------------------------------------------------
__global__ void prep_kernel(const int* __restrict__ adj, const float* __restrict__ Wl) {
    const int j = blockIdx.x;
    const int i = threadIdx.x;
    __shared__ int sdeg[NPAD];
    int a = (i < NN && j < NN) ? (adj[i * NN + j] != 0) : 0;
    sdeg[i] = a;
    __syncthreads();
#pragma unroll
    for (int s = 64; s > 0; s >>= 1) {
        if (i < s) sdeg[i] += sdeg[i + s];
        __syncthreads();
    }
    const int deg = sdeg[0];
    const float inv = (j < NN) ? 1.0f / (float)(deg > 1 ? deg : 1) : 0.0f;
    g_Mn [j * NPAD + i] = a ? inv : 0.0f;
    g_Wlp[j * NPAD + i] = (i < NN && j < NN) ? Wl[j * NN + i] : 0.0f;
}

// ===========================================================================
// tgemm: big GEMM, single fp16 (A and B both fp16, one MMA term).
// CTA tile 128 x BNT, 256 thr, 8 warps (4m x 2n), warp tile 32 x (BNT/2).
// Writes fp32 partials to C + slice*PS.
// ===========================================================================
template<int BNT>
__global__ __launch_bounds__(NTH, 1)
void tgemm(const float* __restrict__ A1, int lda1, int ka1,
           const float* __restrict__ B1, int ldb1,
           const float* __restrict__ A2, int lda2, int ka2,
           const float* __restrict__ B2, int ldb2,
           int SPLITS,
           float* __restrict__ C, int ldc, int Mreal)
{
    constexpr int NTW = BNT / 16;
    constexpr int PITCHB = BNT + 8;
    constexpr int NBG = NTW / 2;
    constexpr int FB = BNT / 16;
    constexpr uint32_t AH_OFF = 0;
    constexpr uint32_t BH_OFF = BM * PITCHA * 2;             // 18432
    constexpr uint32_t BBYTES = (uint32_t)BKC * PITCHB * 2;  // 17408 @BNT=128
    constexpr uint32_t STAGE  = BH_OFF + BBYTES;             // 35840

    extern __shared__ __align__(16) char dsm[];
    const uint32_t sb = smem_u32(dsm);

    const int tid = threadIdx.x;
    const int wid = tid >> 5;
    const int lid = tid & 31;
    const int ms = wid & 3;
    const int ns = wid >> 2;
    const int n0 = blockIdx.x * BNT;
    const int slice = blockIdx.y;

    const int pair = slice / SPLITS;
    const int q    = slice % SPLITS;
    const float* A = pair ? A2 : A1;
    const float* B = pair ? B2 : B1;
    const int lda = pair ? lda2 : lda1;
    const int ldb = pair ? ldb2 : ldb1;
    const int kaeff = (pair ? ka2 : ka1) / SPLITS;
    const int kbase = q * kaeff;
    const int T = kaeff / BKC;

    const int alrow = tid >> 4;
    const int alc   = (tid & 15) * 4;
    const int bkq = tid >> 2;
    const int bnq = (tid & 3) * (BNT / 4);

    float acc[2][NTW][4];
#pragma unroll
    for (int a = 0; a < 2; ++a)
#pragma unroll
        for (int b = 0; b < NTW; ++b)
#pragma unroll
            for (int c = 0; c < 4; ++c) acc[a][b][c] = 0.0f;

    const uint32_t aoffH = AH_OFF +
        (((uint32_t)(ms * 32 + (lid & 15)) * PITCHA) + ((lid >> 4) & 1) * 8u) * 2u;
    const uint32_t boff = BH_OFF +
        (((uint32_t)(lid & 15) * PITCHB) + (uint32_t)(ns * (BNT / 2) + (lid >> 4) * 8)) * 2u;

    float4 fa[8];
    float4 fbr[FB];
    const float4 f4z = make_float4(0.f, 0.f, 0.f, 0.f);

#define LOADG(T_)                                                              \
    do {                                                                       \
        int k0_ = kbase + (T_) * BKC;                                          \
        _Pragma("unroll")                                                      \
        for (int p = 0; p < 8; ++p) {                                          \
            int m = p * 16 + alrow;                                            \
            fa[p] = (m < Mreal) ? *(const float4*)(A + (size_t)m * lda + k0_ + alc) : f4z; \
        }                                                                      \
        const float* p_ = B + (size_t)(k0_ + bkq) * ldb + n0 + bnq;            \
        _Pragma("unroll")                                                      \
        for (int j = 0; j < FB; ++j)                                           \
            fbr[j] = *(const float4*)(p_ + j * 4);                             \
    } while (0)

#define STORE_STAGE(bufsel)                                                    \
    do {                                                                       \
        char* st = dsm + (bufsel) * STAGE;                                     \
        _Pragma("unroll")                                                      \
        for (int p = 0; p < 8; p += 2) {                                       \
            uint4 av;                                                          \
            av.x = cvth2(fa[p].x,     fa[p].y);                                \
            av.y = cvth2(fa[p].z,     fa[p].w);                                \
            av.z = cvth2(fa[p + 1].x, fa[p + 1].y);                            \
            av.w = cvth2(fa[p + 1].z, fa[p + 1].w);                            \
            /* rows p*16+alrow and (p+1)*16+alrow share alc */                 \
            uint32_t r0 = (uint32_t)(p * 16 + alrow);                          \
            uint32_t r1 = (uint32_t)((p + 1) * 16 + alrow);                    \
            uint32_t o0 = (r0 * PITCHA + (uint32_t)alc) * 2u;                  \
            uint32_t o1 = (r1 * PITCHA + (uint32_t)alc) * 2u;                  \
            *(uint2*)(st + AH_OFF + o0) = make_uint2(av.x, av.y);              \
            *(uint2*)(st + AH_OFF + o1) = make_uint2(av.z, av.w);              \
        }                                                                      \
        {                                                                      \
            uint32_t o_ = ((uint32_t)bkq * PITCHB + (uint32_t)bnq) * 2u;       \
            _Pragma("unroll")                                                  \
            for (int j = 0; j < FB; j += 2) {                                  \
                uint4 hv;                                                      \
                hv.x = cvth2(fbr[j].x,     fbr[j].y);                          \
                hv.y = cvth2(fbr[j].z,     fbr[j].w);                          \
                hv.z = cvth2(fbr[j + 1].x, fbr[j + 1].y);                      \
                hv.w = cvth2(fbr[j + 1].z, fbr[j + 1].w);                      \
                *(uint4*)(st + BH_OFF + o_ + j * 8) = hv;                      \
            }                                                                  \
        }                                                                      \
    } while (0)

    LOADG(0);
    STORE_STAGE(0);
    if (T > 1) LOADG(1);
    __syncthreads();

    for (int t = 0; t < T; ++t) {
        const uint32_t base = sb + (uint32_t)(t & 1) * STAGE;
#pragma unroll
        for (int ks = 0; ks < 4; ++ks) {
            const uint32_t kA = (uint32_t)ks * 32u;
            const uint32_t kB = (uint32_t)ks * 16u * PITCHB * 2u;
            uint32_t ah[2][4], bh[NBG][4];
            LDMX4(ah[0], base + aoffH + kA);
            LDMX4(ah[1], base + aoffH + 16u * PITCHA * 2u + kA);
#pragma unroll
            for (int gp = 0; gp < NBG; ++gp)
                LDMX4T(bh[gp], base + boff + gp * 32u + kB);
#pragma unroll
            for (int mt = 0; mt < 2; ++mt)
#pragma unroll
                for (int nt = 0; nt < NTW; ++nt) {
                    const int gp = nt >> 1, ix = (nt & 1) * 2;
                    MMA_F16(acc[mt][nt], ah[mt], bh[gp][ix], bh[gp][ix + 1]);
                }
        }
        if (t + 1 < T) STORE_STAGE((t + 1) & 1);
        if (t + 2 < T) LOADG(t + 2);
        __syncthreads();
    }
#undef LOADG
#undef STORE_STAGE

    const int g  = lid >> 2;
    const int tq = lid & 3;
    float* Pout = C + (size_t)slice * PS;
#pragma unroll
    for (int mt = 0; mt < 2; ++mt) {
#pragma unroll
        for (int nt = 0; nt < NTW; ++nt) {
            int col = n0 + ns * (BNT / 2) + nt * 8 + tq * 2;
#pragma unroll
            for (int half = 0; half < 2; ++half) {
                int m = ms * 32 + mt * 16 + g + half * 8;
                if (m >= Mreal) continue;
                *(float2*)&Pout[(size_t)m * ldc + col] =
                    make_float2(acc[mt][nt][half * 2 + 0], acc[mt][nt][half * 2 + 1]);
            }
        }
    }
}

// ===========================================================================
// tgemm32f: small fused GEMM (bf16 3-term, R12-proven). CTA tile 128x32,
// 256 thr, 8 warps (4m x 2n), warp tile 32x16. K = 128 (T=2).
//   B[k][n] = (brelu? relu : id)( sum_{s<4} P_s[k][n] + bcol[n] )
//   computed in the loader; optionally materialized to hout (rows < NN).
// Epilogue: C = A @ B (+ rowbias per m).
// ===========================================================================
#define BNT32 32
#define PITCHB32 (BNT32 + 8)
#define AH32 0u
#define AL32 ((uint32_t)BM * PITCHA * 2u)            // 18432
#define BH32 (2u * AL32)                             // 36864
#define BB32 ((uint32_t)BKC * PITCHB32 * 2u)         // 5120
#define BL32 (BH32 + BB32)
#define ST32 (BH32 + 2u * BB32)                      // 47104
#define DS32 (2u * ST32)                             // 94208

__global__ __launch_bounds__(NTH, 1)
void tgemm32f(const float* __restrict__ A1,          // 128 x 128, lda = NPAD
              const float* __restrict__ P,           // 4 partial slices
              const float* __restrict__ bcol,        // column bias for B
              int brelu,
              float* __restrict__ hout,              // optional: materialize B
              const float* __restrict__ rowbias,     // optional per-row bias
              float* __restrict__ C, int ldc, int Mreal)
{
    extern __shared__ __align__(16) char dsm[];
    const uint32_t sb = smem_u32(dsm);

    const int tid = threadIdx.x;
    const int wid = tid >> 5;
    const int lid = tid & 31;
    const int ms = wid & 3;
    const int ns = wid >> 2;
    const int n0 = blockIdx.x * BNT32;

    const int T = NPAD / BKC;   // 2

    const int alrow = tid >> 4;
    const int alc   = (tid & 15) * 4;
    const int bkq = tid >> 2;                 // 0..63
    const int bnq = (tid & 3) * 8;            // 0,8,16,24

    float acc[2][2][4];
#pragma unroll
    for (int a = 0; a < 2; ++a)
#pragma unroll
        for (int b = 0; b < 2; ++b)
#pragma unroll
            for (int c = 0; c < 4; ++c) acc[a][b][c] = 0.0f;

    const uint32_t aoffH = AH32 +
        (((uint32_t)(ms * 32 + (lid & 15)) * PITCHA) + ((lid >> 4) & 1) * 8u) * 2u;
    const uint32_t boff = BH32 +
        (((uint32_t)(lid & 15) * PITCHB32) + (uint32_t)(ns * 16 + (lid >> 4) * 8)) * 2u;

    float4 fa[8];
    float4 fbr[2];
    const float4 f4z = make_float4(0.f, 0.f, 0.f, 0.f);

#define LOADG(T_)                                                              \
    do {                                                                       \
        int k0_ = (T_) * BKC;                                                  \
        _Pragma("unroll")                                                      \
        for (int p = 0; p < 8; ++p) {                                          \
            int m = p * 16 + alrow;                                            \
            fa[p] = (m < Mreal) ? *(const float4*)(A1 + (size_t)m * NPAD + k0_ + alc) : f4z; \
        }                                                                      \
        int krow = k0_ + bkq;                                                  \
        const float* pp = P + (size_t)krow * CC + n0 + bnq;                    \
        _Pragma("unroll")                                                      \
        for (int j = 0; j < 2; ++j) {                                          \
            float4 p0 = *(const float4*)(pp + j * 4);                          \
            float4 p1 = *(const float4*)(pp + PS + j * 4);                     \
            float4 p2 = *(const float4*)(pp + 2 * PS + j * 4);                 \
            float4 p3 = *(const float4*)(pp + 3 * PS + j * 4);                 \
            float4 bv = *(const float4*)(bcol + n0 + bnq + j * 4);             \
            float4 v;                                                          \
            v.x = (p0.x + p1.x) + (p2.x + p3.x) + bv.x;                        \
            v.y = (p0.y + p1.y) + (p2.y + p3.y) + bv.y;                        \
            v.z = (p0.z + p1.z) + (p2.z + p3.z) + bv.z;                        \
            v.w = (p0.w + p1.w) + (p2.w + p3.w) + bv.w;                        \
            if (brelu) {                                                       \
                v.x = fmaxf(v.x, 0.f); v.y = fmaxf(v.y, 0.f);                  \
                v.z = fmaxf(v.z, 0.f); v.w = fmaxf(v.w, 0.f);                  \
            }                                                                  \
            fbr[j] = v;                                                        \
        }                                                                      \
        if (hout != nullptr && krow < NN) {                                    \
            float* ho = hout + (size_t)krow * CC + n0 + bnq;                   \
            *(float4*)(ho)     = fbr[0];                                       \
            *(float4*)(ho + 4) = fbr[1];                                       \
        }                                                                      \
    } while (0)

#define STORE_STAGE(bufsel)                                                    \
    do {                                                                       \
        char* st = dsm + (bufsel) * ST32;                                      \
        _Pragma("unroll")                                                      \
        for (int p = 0; p < 8; ++p) {                                          \
            int row = p * 16 + alrow;                                          \
            uint32_t h0, l0, h1, l1;                                           \
            split2(fa[p].x, fa[p].y, h0, l0);                                  \
            split2(fa[p].z, fa[p].w, h1, l1);                                  \
            uint32_t off = ((uint32_t)row * PITCHA + (uint32_t)alc) * 2u;      \
            *(uint2*)(st + AH32 + off) = make_uint2(h0, h1);                   \
            *(uint2*)(st + AL32 + off) = make_uint2(l0, l1);                   \
        }                                                                      \
        {                                                                      \
            uint32_t o_ = ((uint32_t)bkq * PITCHB32 + (uint32_t)bnq) * 2u;     \
            uint4 hv, lv;                                                      \
            split2(fbr[0].x, fbr[0].y, hv.x, lv.x);                            \
            split2(fbr[0].z, fbr[0].w, hv.y, lv.y);                            \
            split2(fbr[1].x, fbr[1].y, hv.z, lv.z);                            \
            split2(fbr[1].z, fbr[1].w, hv.w, lv.w);                            \
            *(uint4*)(st + BH32 + o_) = hv;                                    \
            *(uint4*)(st + BL32 + o_) = lv;                                    \
        }                                                                      \
    } while (0)

    LOADG(0);
    STORE_STAGE(0);
    LOADG(1);
    __syncthreads();

    for (int t = 0; t < T; ++t) {
        const uint32_t base = sb + (uint32_t)(t & 1) * ST32;
#pragma unroll
        for (int ks = 0; ks < 4; ++ks) {
            const uint32_t kA = (uint32_t)ks * 32u;
            const uint32_t kB = (uint32_t)ks * 16u * PITCHB32 * 2u;
            uint32_t ah[2][4], al[2][4], bh[4], bl[4];
            LDMX4(ah[0], base + aoffH + kA);
            LDMX4(ah[1], base + aoffH + 16u * PITCHA * 2u + kA);
            LDMX4(al[0], base + aoffH + (AL32 - AH32) + kA);
            LDMX4(al[1], base + aoffH + (AL32 - AH32) + 16u * PITCHA * 2u + kA);
            LDMX4T(bh, base + boff + kB);
            LDMX4T(bl, base + boff + (BL32 - BH32) + kB);
#pragma unroll
            for (int mt = 0; mt < 2; ++mt)
#pragma unroll
                for (int nt = 0; nt < 2; ++nt) {
                    const int ix = nt * 2;
                    MMA_BF16(acc[mt][nt], ah[mt], bh[ix], bh[ix + 1]);
                    MMA_BF16(acc[mt][nt], ah[mt], bl[ix], bl[ix + 1]);
                    MMA_BF16(acc[mt][nt], al[mt], bh[ix], bh[ix + 1]);
                }
        }
        if (t + 1 < T) STORE_STAGE((t + 1) & 1);
        __syncthreads();
    }
#undef LOADG
#undef STORE_STAGE

    const int g  = lid >> 2;
    const int tq = lid & 3;
#pragma unroll
    for (int mt = 0; mt < 2; ++mt) {
#pragma unroll
        for (int nt = 0; nt < 2; ++nt) {
            int col = n0 + ns * 16 + nt * 8 + tq * 2;
#pragma unroll
            for (int half = 0; half < 2; ++half) {
                int m = ms * 32 + mt * 16 + g + half * 8;
                if (m >= Mreal) continue;
                float rb = (rowbias != nullptr) ? rowbias[m] : 0.0f;
                float vx = acc[mt][nt][half * 2 + 0] + rb;
                float vy = acc[mt][nt][half * 2 + 1] + rb;
                *(float2*)&C[(size_t)m * ldc + col] = make_float2(vx, vy);
            }
        }
    }
}

// ---------------------------------------------------------------------------
extern "C" void kernel_launch(void* const* d_in, const int* in_sizes, int n_in,
                              void* d_out, int out_size)
{
    const float* x   = (const float*)d_in[0];
    const int*   adj = (const int*)  d_in[1];
    const float* W2  = (const float*)d_in[2];
    const float* b2  = (const float*)d_in[3];
    const float* W1  = (const float*)d_in[4];
    const float* b1  = (const float*)d_in[5];
    const float* Wl  = (const float*)d_in[6];
    const float* bl  = (const float*)d_in[7];
    float* out = (float*)d_out;

    float *h, *aggr, *Mn, *Wlp, *P;
    cudaGetSymbolAddress((void**)&h,    g_h);
    cudaGetSymbolAddress((void**)&aggr, g_aggr);
    cudaGetSymbolAddress((void**)&Mn,   g_Mn);
    cudaGetSymbolAddress((void**)&Wlp,  g_Wlp);
    cudaGetSymbolAddress((void**)&P,    g_P);

    // single-fp16 stage: AH + BH only
    const int DS128 = 2 * (BM * PITCHA * 2 + BKC * (128 + 8) * 2);   // 71680
    cudaFuncSetAttribute(tgemm<128>, cudaFuncAttributeMaxDynamicSharedMemorySize, DS128);
    cudaFuncSetAttribute(tgemm32f, cudaFuncAttributeMaxDynamicSharedMemorySize, DS32);

    dim3 b(NTH);
    dim3 gBig(CC / 128, 4);    // 32 x 4 slices = 128 CTAs
    dim3 gF  (CC / BNT32);     // 128 CTAs

    prep_kernel<<<NPAD, NPAD>>>(adj, Wl);

    // K1: P_s = x @ W2 over 4 k-slices of 1024 (single fp16)
    tgemm<128><<<gBig, b, DS128>>>(x, CC, CC, W2, CC,
                                   nullptr, 0, 0, nullptr, 0,
                                   /*SPLITS=*/4, P, CC, NN);

    // K2 (fused): B = h = sum P + b2 (materialized to g_h); aggr = Mn @ h
    tgemm32f<<<gF, b, DS32>>>(Mn, P, b2, /*brelu=*/0,
                              /*hout=*/h, /*rowbias=*/nullptr,
                              aggr, CC, NN);

    // K3: P_s = (h @ W1_top | aggr @ W1_bot), each pair split in 2 (single fp16)
    tgemm<128><<<gBig, b, DS128>>>(h, CC, CC, W1, CC,
                                   aggr, CC, CC, W1 + (size_t)CC * CC, CC,
                                   /*SPLITS=*/2, P, CC, NN);

    // K4 (fused): B = out1 = relu(sum P + b1) (never materialized);
    //             out = Wlp @ out1 + bl[:,None]
    tgemm32f<<<gF, b, DS32>>>(Wlp, P, b1, /*brelu=*/1,
                              /*hout=*/nullptr, /*rowbias=*/bl,
                              out, CC, NN);
}